// round 1
// baseline (speedup 1.0000x reference)
#include <cuda_runtime.h>
#include <math.h>

// ---------------------------------------------------------------------------
// SubSample attention block, fp32 baseline.
// Pipeline:
//   1. affine prep (fold BN into per-channel scale/bias)  x5
//   2. xq = x[:, :, ::2, ::2]
//   3. kv  = BN(kv_w @ x)            [B,1280,1024]
//   4. q   = BN(q_w @ xq)            [B,256,256] -> transpose to qT[bh][q][d]
//   5. S   = (qT @ k) * scale        [bh,256,1024]
//   6. softmax rows (1024)
//   7. o   = gelu(v @ att^T)         [bh,128,256] laid out as [B,1024,256]
//   8. mg  = BN(mg_w @ o)            [B,512,256]
//   9. f1  = gelu(BN(fc1_w @ mg))    [B,1024,256]
//  10. out = BN(fc2_w @ f1)          [B,512,256]
// All GEMMs share one 128x128x8 tiled SGEMM (8x8 microtile, 256 thr) with
// compile-time epilogue flags and optional B-transposed loads.
// ---------------------------------------------------------------------------

constexpr int BATCH = 32, CIN = 256, NP = 1024, QP = 256;
constexpr int HEADS = 8, KD = 32, VD = 128;
constexpr int KVC = (KD + VD) * HEADS;   // 1280
constexpr int QC  = HEADS * KD;          // 256
constexpr int MERGE = HEADS * VD;        // 1024
constexpr int DOUT = 512, HID = 1024;

// Scratch (device globals: no allocation allowed in kernel_launch)
__device__ __align__(16) float g_kv [(size_t)BATCH * KVC * NP];      // 167.8 MB
__device__ __align__(16) float g_xq [(size_t)BATCH * CIN * QP];      // 8.4 MB
__device__ __align__(16) float g_q  [(size_t)BATCH * QC  * QP];      // 8.4 MB
__device__ __align__(16) float g_qT [(size_t)BATCH * HEADS * QP * KD]; // 8.4 MB
__device__ __align__(16) float g_att[(size_t)BATCH * HEADS * QP * NP]; // 268 MB
__device__ __align__(16) float g_o  [(size_t)BATCH * MERGE * QP];    // 33.5 MB
__device__ __align__(16) float g_mg [(size_t)BATCH * DOUT * QP];     // 16.8 MB
__device__ __align__(16) float g_f1 [(size_t)BATCH * HID  * QP];     // 33.5 MB
// folded BN params: [kv:0..1280) [q:1280..1536) [mg:1536..2048) [bn1:2048..3072) [bn2:3072..3584)
__device__ float g_sc[3584];
__device__ float g_bi[3584];

__device__ __forceinline__ float gelu_exact(float x) {
    return 0.5f * x * (1.0f + erff(x * 0.70710678118654752f));
}

__global__ void affine_prep(const float* __restrict__ g, const float* __restrict__ b,
                            const float* __restrict__ m, const float* __restrict__ v,
                            float* __restrict__ sc, float* __restrict__ bi, int n) {
    int i = blockIdx.x * blockDim.x + threadIdx.x;
    if (i < n) {
        float s = g[i] * rsqrtf(v[i] + 1e-5f);
        sc[i] = s;
        bi[i] = b[i] - m[i] * s;
    }
}

// xq[b][c][qy*16+qx] = x[b][c][(2qy)*32 + 2qx]
__global__ void subsample_k(const float* __restrict__ x, float* __restrict__ xq) {
    int i = blockIdx.x * 256 + threadIdx.x;       // BATCH*CIN*QP = 2,097,152
    int qp = i & 255;
    int bc = i >> 8;
    int qy = qp >> 4, qx = qp & 15;
    xq[i] = x[((size_t)bc << 10) + (qy << 6) + (qx << 1)];
}

// qT[(b*8+h)*256 + qp][d] = q[b][h*32+d][qp]
__global__ void qtrans_k(const float* __restrict__ q, float* __restrict__ qT) {
    int i = blockIdx.x * 256 + threadIdx.x;       // 2,097,152
    int d  = i & 31;
    int qp = (i >> 5) & 255;
    int z  = i >> 13;                              // b*8+h
    int b = z >> 3, h = z & 7;
    qT[i] = q[(((size_t)b * QC + h * KD + d) << 8) + qp];
}

// In-place softmax over rows of length 1024. One warp per row.
__global__ void softmax_k(float* __restrict__ att) {
    int gw   = (blockIdx.x * 256 + threadIdx.x) >> 5;  // row id, 65536 rows
    int lane = threadIdx.x & 31;
    float4* row = reinterpret_cast<float4*>(att + (size_t)gw * NP);
    float4 v[8];
    float mx = -1e30f;
#pragma unroll
    for (int r = 0; r < 8; r++) {
        v[r] = row[lane + 32 * r];
        mx = fmaxf(mx, fmaxf(fmaxf(v[r].x, v[r].y), fmaxf(v[r].z, v[r].w)));
    }
#pragma unroll
    for (int off = 16; off >= 1; off >>= 1)
        mx = fmaxf(mx, __shfl_xor_sync(0xffffffffu, mx, off));
    float sum = 0.0f;
#pragma unroll
    for (int r = 0; r < 8; r++) {
        v[r].x = expf(v[r].x - mx); v[r].y = expf(v[r].y - mx);
        v[r].z = expf(v[r].z - mx); v[r].w = expf(v[r].w - mx);
        sum += v[r].x + v[r].y + v[r].z + v[r].w;
    }
#pragma unroll
    for (int off = 16; off >= 1; off >>= 1)
        sum += __shfl_xor_sync(0xffffffffu, sum, off);
    float inv = 1.0f / sum;
#pragma unroll
    for (int r = 0; r < 8; r++) {
        v[r].x *= inv; v[r].y *= inv; v[r].z *= inv; v[r].w *= inv;
        row[lane + 32 * r] = v[r];
    }
}

// ---------------------------------------------------------------------------
// Tiled SGEMM: C[z][m][n] = sum_k A[z][m][k] * B[z][k][n]   (BT=false)
//                         = sum_k A[z][m][k] * B[z][n][k]   (BT=true, B stored [n][k])
// 128x128 block tile, BK=8, 256 threads, 8x8 per-thread microtile.
// Requires M%128==0, N%128==0, K%8==0 (all shapes here satisfy this).
// Epilogue: optional *cmul, then optional per-row affine, then optional gelu.
// ---------------------------------------------------------------------------
template <bool BT, bool AFF, bool GEL, bool SCL>
__global__ __launch_bounds__(256, 2)
void gemm128(const float* __restrict__ A, const float* __restrict__ B,
             float* __restrict__ C,
             int M, int N, int K, int lda, int ldb, int ldc,
             long long sA, long long sB, long long sC,
             const float* __restrict__ scale, const float* __restrict__ bias,
             float cmul) {
    A += (long long)blockIdx.z * sA;
    B += (long long)blockIdx.z * sB;
    C += (long long)blockIdx.z * sC;
    const int bm = blockIdx.y * 128;
    const int bn = blockIdx.x * 128;

    __shared__ float As[8][128];
    __shared__ float Bs[8][128];

    const int t  = threadIdx.x;
    const int tx = t & 15;          // column group
    const int ty = t >> 4;          // row group

    float acc[8][8];
#pragma unroll
    for (int i = 0; i < 8; i++)
#pragma unroll
        for (int j = 0; j < 8; j++) acc[i][j] = 0.0f;

    // A tile load mapping: 128 rows x 8 k, one float4 per thread along k
    const int arow = t >> 1;
    const int acol = (t & 1) * 4;
    const float* Aptr = A + (long long)(bm + arow) * lda + acol;

    // B tile load mapping
    const float* Bptr;
    int brow, bcol;
    if (BT) {            // B stored [ncol][k]: like A, transpose into Bs
        brow = t >> 1;               // n within tile
        bcol = (t & 1) * 4;          // k
        Bptr = B + (long long)(bn + brow) * ldb + bcol;
    } else {             // B stored [k][n]: direct vectorized
        brow = t >> 5;               // k (0..7)
        bcol = (t & 31) * 4;         // n
        Bptr = B + (long long)brow * ldb + bn + bcol;
    }

    for (int k0 = 0; k0 < K; k0 += 8) {
        float4 av = *reinterpret_cast<const float4*>(Aptr + k0);
        As[acol + 0][arow] = av.x;
        As[acol + 1][arow] = av.y;
        As[acol + 2][arow] = av.z;
        As[acol + 3][arow] = av.w;
        if (BT) {
            float4 bv = *reinterpret_cast<const float4*>(Bptr + k0);
            Bs[bcol + 0][brow] = bv.x;
            Bs[bcol + 1][brow] = bv.y;
            Bs[bcol + 2][brow] = bv.z;
            Bs[bcol + 3][brow] = bv.w;
        } else {
            float4 bv = *reinterpret_cast<const float4*>(Bptr + (long long)k0 * ldb);
            *reinterpret_cast<float4*>(&Bs[brow][bcol]) = bv;
        }
        __syncthreads();
#pragma unroll
        for (int kk = 0; kk < 8; kk++) {
            float a[8], b[8];
            *reinterpret_cast<float4*>(a)     = *reinterpret_cast<float4*>(&As[kk][ty * 8]);
            *reinterpret_cast<float4*>(a + 4) = *reinterpret_cast<float4*>(&As[kk][ty * 8 + 4]);
            *reinterpret_cast<float4*>(b)     = *reinterpret_cast<float4*>(&Bs[kk][tx * 8]);
            *reinterpret_cast<float4*>(b + 4) = *reinterpret_cast<float4*>(&Bs[kk][tx * 8 + 4]);
#pragma unroll
            for (int i = 0; i < 8; i++)
#pragma unroll
                for (int j = 0; j < 8; j++)
                    acc[i][j] = fmaf(a[i], b[j], acc[i][j]);
        }
        __syncthreads();
    }

    // epilogue
#pragma unroll
    for (int i = 0; i < 8; i++) {
        const int m = bm + ty * 8 + i;
        float s = 1.0f, bb = 0.0f;
        if (AFF) { s = scale[m]; bb = bias[m]; }
        float out[8];
#pragma unroll
        for (int j = 0; j < 8; j++) {
            float v = acc[i][j];
            if (SCL) v *= cmul;
            if (AFF) v = fmaf(v, s, bb);
            if (GEL) v = gelu_exact(v);
            out[j] = v;
        }
        float* cp = C + (long long)m * ldc + bn + tx * 8;
        *reinterpret_cast<float4*>(cp)     = *reinterpret_cast<float4*>(out);
        *reinterpret_cast<float4*>(cp + 4) = *reinterpret_cast<float4*>(out + 4);
    }
}

// ---------------------------------------------------------------------------
extern "C" void kernel_launch(void* const* d_in, const int* in_sizes, int n_in,
                              void* d_out, int out_size) {
    const float* x     = (const float*)d_in[0];
    const float* kv_w  = (const float*)d_in[1];
    const float* q_w   = (const float*)d_in[6];
    const float* mg_w  = (const float*)d_in[11];
    const float* fc1_w = (const float*)d_in[16];
    const float* fc2_w = (const float*)d_in[21];
    float* out = (float*)d_out;

    float *kv, *xq, *q, *qT, *att, *o, *mg, *f1, *sc, *bi;
    cudaGetSymbolAddress((void**)&kv,  g_kv);
    cudaGetSymbolAddress((void**)&xq,  g_xq);
    cudaGetSymbolAddress((void**)&q,   g_q);
    cudaGetSymbolAddress((void**)&qT,  g_qT);
    cudaGetSymbolAddress((void**)&att, g_att);
    cudaGetSymbolAddress((void**)&o,   g_o);
    cudaGetSymbolAddress((void**)&mg,  g_mg);
    cudaGetSymbolAddress((void**)&f1,  g_f1);
    cudaGetSymbolAddress((void**)&sc,  g_sc);
    cudaGetSymbolAddress((void**)&bi,  g_bi);

    // 1) fold BN params
    affine_prep<<<5, 256>>>((const float*)d_in[2], (const float*)d_in[3],
                            (const float*)d_in[4], (const float*)d_in[5],
                            sc + 0, bi + 0, KVC);
    affine_prep<<<1, 256>>>((const float*)d_in[7], (const float*)d_in[8],
                            (const float*)d_in[9], (const float*)d_in[10],
                            sc + 1280, bi + 1280, QC);
    affine_prep<<<2, 256>>>((const float*)d_in[12], (const float*)d_in[13],
                            (const float*)d_in[14], (const float*)d_in[15],
                            sc + 1536, bi + 1536, DOUT);
    affine_prep<<<4, 256>>>((const float*)d_in[17], (const float*)d_in[18],
                            (const float*)d_in[19], (const float*)d_in[20],
                            sc + 2048, bi + 2048, HID);
    affine_prep<<<2, 256>>>((const float*)d_in[22], (const float*)d_in[23],
                            (const float*)d_in[24], (const float*)d_in[25],
                            sc + 3072, bi + 3072, DOUT);

    // 2) subsample x -> xq
    subsample_k<<<(BATCH * CIN * QP) / 256, 256>>>(x, xq);

    // 3) kv = BN(kv_w @ x) : M=1280, N=1024, K=256, per batch
    gemm128<false, true, false, false>
        <<<dim3(NP / 128, KVC / 128, BATCH), 256>>>(
            kv_w, x, kv, KVC, NP, CIN, CIN, NP, NP,
            0LL, (long long)CIN * NP, (long long)KVC * NP, sc + 0, bi + 0, 1.0f);

    // 4) q = BN(q_w @ xq) : M=256, N=256, K=256, per batch; then transpose
    gemm128<false, true, false, false>
        <<<dim3(QP / 128, QC / 128, BATCH), 256>>>(
            q_w, xq, q, QC, QP, CIN, CIN, QP, QP,
            0LL, (long long)CIN * QP, (long long)QC * QP, sc + 1280, bi + 1280, 1.0f);
    qtrans_k<<<(BATCH * HEADS * QP * KD) / 256, 256>>>(q, qT);

    // 5) S = (qT @ k) * scale : per (b,h): M=256(q), N=1024(n), K=32(d)
    gemm128<false, false, false, true>
        <<<dim3(NP / 128, QP / 128, BATCH * HEADS), 256>>>(
            qT, kv, att, QP, NP, KD, KD, NP, NP,
            (long long)QP * KD, (long long)(KD + VD) * NP, (long long)QP * NP,
            nullptr, nullptr, 0.17677669529663687f);

    // 6) softmax over n
    softmax_k<<<(BATCH * HEADS * QP) / 8, 256>>>(att);

    // 7) o = gelu(v @ att^T) : per (b,h): M=128(vd), N=256(q), K=1024(n); B transposed
    gemm128<true, false, true, false>
        <<<dim3(QP / 128, VD / 128, BATCH * HEADS), 256>>>(
            kv + (long long)KD * NP, att, o, VD, QP, NP, NP, NP, QP,
            (long long)(KD + VD) * NP, (long long)QP * NP, (long long)VD * QP,
            nullptr, nullptr, 1.0f);

    // 8) mg = BN(mg_w @ o) : M=512, N=256, K=1024, per batch
    gemm128<false, true, false, false>
        <<<dim3(QP / 128, DOUT / 128, BATCH), 256>>>(
            mg_w, o, mg, DOUT, QP, MERGE, MERGE, QP, QP,
            0LL, (long long)MERGE * QP, (long long)DOUT * QP, sc + 1536, bi + 1536, 1.0f);

    // 9) f1 = gelu(BN(fc1_w @ mg)) : M=1024, N=256, K=512
    gemm128<false, true, true, false>
        <<<dim3(QP / 128, HID / 128, BATCH), 256>>>(
            fc1_w, mg, f1, HID, QP, DOUT, DOUT, QP, QP,
            0LL, (long long)DOUT * QP, (long long)HID * QP, sc + 2048, bi + 2048, 1.0f);

    // 10) out = BN(fc2_w @ f1) : M=512, N=256, K=1024
    gemm128<false, true, false, false>
        <<<dim3(QP / 128, DOUT / 128, BATCH), 256>>>(
            fc2_w, f1, out, DOUT, QP, HID, HID, QP, QP,
            0LL, (long long)HID * QP, (long long)DOUT * QP, sc + 3072, bi + 3072, 1.0f);
}

// round 2
// speedup vs baseline: 2.0118x; 2.0118x over previous
#include <cuda_runtime.h>
#include <math.h>

// ---------------------------------------------------------------------------
// SubSample attention block — tf32 tensor-core version (mma.sync.m16n8k8).
// Same pipeline as the fp32 baseline; all 7 GEMM launches now run on the
// tensor pipe with fp32 accumulation. Inputs converted f32->tf32 (cvt.rna)
// once when staged into shared memory.
// ---------------------------------------------------------------------------

constexpr int BATCH = 32, CIN = 256, NP = 1024, QP = 256;
constexpr int HEADS = 8, KD = 32, VD = 128;
constexpr int KVC = (KD + VD) * HEADS;   // 1280
constexpr int QC  = HEADS * KD;          // 256
constexpr int MERGE = HEADS * VD;        // 1024
constexpr int DOUT = 512, HID = 1024;

__device__ __align__(16) float g_kv [(size_t)BATCH * KVC * NP];
__device__ __align__(16) float g_xq [(size_t)BATCH * CIN * QP];
__device__ __align__(16) float g_q  [(size_t)BATCH * QC  * QP];
__device__ __align__(16) float g_qT [(size_t)BATCH * HEADS * QP * KD];
__device__ __align__(16) float g_att[(size_t)BATCH * HEADS * QP * NP];
__device__ __align__(16) float g_o  [(size_t)BATCH * MERGE * QP];
__device__ __align__(16) float g_mg [(size_t)BATCH * DOUT * QP];
__device__ __align__(16) float g_f1 [(size_t)BATCH * HID  * QP];
__device__ float g_sc[3584];
__device__ float g_bi[3584];

__device__ __forceinline__ float gelu_exact(float x) {
    return 0.5f * x * (1.0f + erff(x * 0.70710678118654752f));
}

__device__ __forceinline__ unsigned f2tf(float x) {
    unsigned r;
    asm("cvt.rna.tf32.f32 %0, %1;" : "=r"(r) : "f"(x));
    return r;
}

__global__ void affine_prep(const float* __restrict__ g, const float* __restrict__ b,
                            const float* __restrict__ m, const float* __restrict__ v,
                            float* __restrict__ sc, float* __restrict__ bi, int n) {
    int i = blockIdx.x * blockDim.x + threadIdx.x;
    if (i < n) {
        float s = g[i] * rsqrtf(v[i] + 1e-5f);
        sc[i] = s;
        bi[i] = b[i] - m[i] * s;
    }
}

__global__ void subsample_k(const float* __restrict__ x, float* __restrict__ xq) {
    int i = blockIdx.x * 256 + threadIdx.x;
    int qp = i & 255;
    int bc = i >> 8;
    int qy = qp >> 4, qx = qp & 15;
    xq[i] = x[((size_t)bc << 10) + (qy << 6) + (qx << 1)];
}

__global__ void qtrans_k(const float* __restrict__ q, float* __restrict__ qT) {
    int i = blockIdx.x * 256 + threadIdx.x;
    int d  = i & 31;
    int qp = (i >> 5) & 255;
    int z  = i >> 13;
    int b = z >> 3, h = z & 7;
    qT[i] = q[(((size_t)b * QC + h * KD + d) << 8) + qp];
}

__global__ void softmax_k(float* __restrict__ att) {
    int gw   = (blockIdx.x * 256 + threadIdx.x) >> 5;
    int lane = threadIdx.x & 31;
    float4* row = reinterpret_cast<float4*>(att + (size_t)gw * NP);
    float4 v[8];
    float mx = -1e30f;
#pragma unroll
    for (int r = 0; r < 8; r++) {
        v[r] = row[lane + 32 * r];
        mx = fmaxf(mx, fmaxf(fmaxf(v[r].x, v[r].y), fmaxf(v[r].z, v[r].w)));
    }
#pragma unroll
    for (int off = 16; off >= 1; off >>= 1)
        mx = fmaxf(mx, __shfl_xor_sync(0xffffffffu, mx, off));
    float sum = 0.0f;
#pragma unroll
    for (int r = 0; r < 8; r++) {
        v[r].x = expf(v[r].x - mx); v[r].y = expf(v[r].y - mx);
        v[r].z = expf(v[r].z - mx); v[r].w = expf(v[r].w - mx);
        sum += v[r].x + v[r].y + v[r].z + v[r].w;
    }
#pragma unroll
    for (int off = 16; off >= 1; off >>= 1)
        sum += __shfl_xor_sync(0xffffffffu, sum, off);
    float inv = 1.0f / sum;
#pragma unroll
    for (int r = 0; r < 8; r++) {
        v[r].x *= inv; v[r].y *= inv; v[r].z *= inv; v[r].w *= inv;
        row[lane + 32 * r] = v[r];
    }
}

// ---------------------------------------------------------------------------
// tf32 tensor-core GEMM: C[z] = A[z] @ B[z] (BT=false, B stored [k][n])
//                              = A[z] @ B[z]^T (BT=true, B stored [n][k])
// 128x128 block tile, BK=32, 256 threads = 8 warps (2M x 4N), warp tile 64x32.
// mma.sync.aligned.m16n8k8.row.col.f32.tf32.tf32.f32, fp32 accumulate.
// Smem strides: As 36 floats/row, Bs 136 floats/row (conflict-free frag LDS).
// ---------------------------------------------------------------------------
template <bool BT, bool AFF, bool GEL, bool SCL>
__global__ __launch_bounds__(256, 2)
void tgemm(const float* __restrict__ A, const float* __restrict__ B,
           float* __restrict__ C,
           int M, int N, int K, int lda, int ldb, int ldc,
           long long sA, long long sB, long long sC,
           const float* __restrict__ scale, const float* __restrict__ bias,
           float cmul) {
    A += (long long)blockIdx.z * sA;
    B += (long long)blockIdx.z * sB;
    C += (long long)blockIdx.z * sC;
    const int bm = blockIdx.y * 128;
    const int bn = blockIdx.x * 128;

    __shared__ float As[128][36];   // [m][k], tf32 bits
    __shared__ float Bs[32][136];   // [k][n], tf32 bits

    const int t    = threadIdx.x;
    const int warp = t >> 5, lane = t & 31;
    const int wm   = warp & 1;          // 0..1 (M)
    const int wn   = warp >> 1;         // 0..3 (N)
    const int quad = lane >> 2, tq = lane & 3;

    float acc[4][4][4];
#pragma unroll
    for (int i = 0; i < 4; i++)
#pragma unroll
        for (int j = 0; j < 4; j++)
#pragma unroll
            for (int r = 0; r < 4; r++) acc[i][j][r] = 0.0f;

    for (int k0 = 0; k0 < K; k0 += 32) {
        // stage A: 128 x 32, f32 -> tf32
#pragma unroll
        for (int j = 0; j < 4; j++) {
            int idx = j * 256 + t;
            int r  = idx & 127;
            int kc = (idx >> 7) * 4;
            float4 v = *reinterpret_cast<const float4*>(A + (long long)(bm + r) * lda + k0 + kc);
            As[r][kc + 0] = __uint_as_float(f2tf(v.x));
            As[r][kc + 1] = __uint_as_float(f2tf(v.y));
            As[r][kc + 2] = __uint_as_float(f2tf(v.z));
            As[r][kc + 3] = __uint_as_float(f2tf(v.w));
        }
        // stage B: 32 x 128
        if (BT) {
#pragma unroll
            for (int j = 0; j < 4; j++) {
                int idx = j * 256 + t;
                int n  = idx & 127;
                int kc = (idx >> 7) * 4;
                float4 v = *reinterpret_cast<const float4*>(B + (long long)(bn + n) * ldb + k0 + kc);
                Bs[kc + 0][n] = __uint_as_float(f2tf(v.x));
                Bs[kc + 1][n] = __uint_as_float(f2tf(v.y));
                Bs[kc + 2][n] = __uint_as_float(f2tf(v.z));
                Bs[kc + 3][n] = __uint_as_float(f2tf(v.w));
            }
        } else {
#pragma unroll
            for (int j = 0; j < 4; j++) {
                int idx = j * 256 + t;
                int n4 = idx & 31;
                int kr = idx >> 5;
                float4 v = *reinterpret_cast<const float4*>(B + (long long)(k0 + kr) * ldb + bn + n4 * 4);
                Bs[kr][n4 * 4 + 0] = __uint_as_float(f2tf(v.x));
                Bs[kr][n4 * 4 + 1] = __uint_as_float(f2tf(v.y));
                Bs[kr][n4 * 4 + 2] = __uint_as_float(f2tf(v.z));
                Bs[kr][n4 * 4 + 3] = __uint_as_float(f2tf(v.w));
            }
        }
        __syncthreads();

#pragma unroll
        for (int kk = 0; kk < 4; kk++) {
            const int kb = kk * 8;
            unsigned a[4][4];
#pragma unroll
            for (int mi = 0; mi < 4; mi++) {
                int r = wm * 64 + mi * 16 + quad;
                int c = kb + tq;
                a[mi][0] = __float_as_uint(As[r][c]);
                a[mi][1] = __float_as_uint(As[r + 8][c]);
                a[mi][2] = __float_as_uint(As[r][c + 4]);
                a[mi][3] = __float_as_uint(As[r + 8][c + 4]);
            }
            unsigned b[4][2];
#pragma unroll
            for (int ni = 0; ni < 4; ni++) {
                int nn = wn * 32 + ni * 8 + quad;
                b[ni][0] = __float_as_uint(Bs[kb + tq][nn]);
                b[ni][1] = __float_as_uint(Bs[kb + tq + 4][nn]);
            }
#pragma unroll
            for (int mi = 0; mi < 4; mi++)
#pragma unroll
                for (int ni = 0; ni < 4; ni++) {
                    asm volatile(
                        "mma.sync.aligned.m16n8k8.row.col.f32.tf32.tf32.f32 "
                        "{%0,%1,%2,%3}, {%4,%5,%6,%7}, {%8,%9}, {%0,%1,%2,%3};"
                        : "+f"(acc[mi][ni][0]), "+f"(acc[mi][ni][1]),
                          "+f"(acc[mi][ni][2]), "+f"(acc[mi][ni][3])
                        : "r"(a[mi][0]), "r"(a[mi][1]), "r"(a[mi][2]), "r"(a[mi][3]),
                          "r"(b[ni][0]), "r"(b[ni][1]));
                }
        }
        __syncthreads();
    }

    // epilogue: c0,c1 -> (row, col..col+1), c2,c3 -> (row+8, col..col+1)
#pragma unroll
    for (int mi = 0; mi < 4; mi++) {
        int r0 = bm + wm * 64 + mi * 16 + quad;
        int r1 = r0 + 8;
        float s0 = 1.0f, b0 = 0.0f, s1 = 1.0f, b1 = 0.0f;
        if (AFF) { s0 = scale[r0]; b0 = bias[r0]; s1 = scale[r1]; b1 = bias[r1]; }
#pragma unroll
        for (int ni = 0; ni < 4; ni++) {
            int col = bn + wn * 32 + ni * 8 + 2 * tq;
            float v0 = acc[mi][ni][0], v1 = acc[mi][ni][1];
            float v2 = acc[mi][ni][2], v3 = acc[mi][ni][3];
            if (SCL) { v0 *= cmul; v1 *= cmul; v2 *= cmul; v3 *= cmul; }
            if (AFF) {
                v0 = fmaf(v0, s0, b0); v1 = fmaf(v1, s0, b0);
                v2 = fmaf(v2, s1, b1); v3 = fmaf(v3, s1, b1);
            }
            if (GEL) {
                v0 = gelu_exact(v0); v1 = gelu_exact(v1);
                v2 = gelu_exact(v2); v3 = gelu_exact(v3);
            }
            float2 p0 = make_float2(v0, v1);
            float2 p1 = make_float2(v2, v3);
            *reinterpret_cast<float2*>(C + (long long)r0 * ldc + col) = p0;
            *reinterpret_cast<float2*>(C + (long long)r1 * ldc + col) = p1;
        }
    }
}

// ---------------------------------------------------------------------------
extern "C" void kernel_launch(void* const* d_in, const int* in_sizes, int n_in,
                              void* d_out, int out_size) {
    const float* x     = (const float*)d_in[0];
    const float* kv_w  = (const float*)d_in[1];
    const float* q_w   = (const float*)d_in[6];
    const float* mg_w  = (const float*)d_in[11];
    const float* fc1_w = (const float*)d_in[16];
    const float* fc2_w = (const float*)d_in[21];
    float* out = (float*)d_out;

    float *kv, *xq, *q, *qT, *att, *o, *mg, *f1, *sc, *bi;
    cudaGetSymbolAddress((void**)&kv,  g_kv);
    cudaGetSymbolAddress((void**)&xq,  g_xq);
    cudaGetSymbolAddress((void**)&q,   g_q);
    cudaGetSymbolAddress((void**)&qT,  g_qT);
    cudaGetSymbolAddress((void**)&att, g_att);
    cudaGetSymbolAddress((void**)&o,   g_o);
    cudaGetSymbolAddress((void**)&mg,  g_mg);
    cudaGetSymbolAddress((void**)&f1,  g_f1);
    cudaGetSymbolAddress((void**)&sc,  g_sc);
    cudaGetSymbolAddress((void**)&bi,  g_bi);

    affine_prep<<<5, 256>>>((const float*)d_in[2], (const float*)d_in[3],
                            (const float*)d_in[4], (const float*)d_in[5],
                            sc + 0, bi + 0, KVC);
    affine_prep<<<1, 256>>>((const float*)d_in[7], (const float*)d_in[8],
                            (const float*)d_in[9], (const float*)d_in[10],
                            sc + 1280, bi + 1280, QC);
    affine_prep<<<2, 256>>>((const float*)d_in[12], (const float*)d_in[13],
                            (const float*)d_in[14], (const float*)d_in[15],
                            sc + 1536, bi + 1536, DOUT);
    affine_prep<<<4, 256>>>((const float*)d_in[17], (const float*)d_in[18],
                            (const float*)d_in[19], (const float*)d_in[20],
                            sc + 2048, bi + 2048, HID);
    affine_prep<<<2, 256>>>((const float*)d_in[22], (const float*)d_in[23],
                            (const float*)d_in[24], (const float*)d_in[25],
                            sc + 3072, bi + 3072, DOUT);

    subsample_k<<<(BATCH * CIN * QP) / 256, 256>>>(x, xq);

    // kv = BN(kv_w @ x)
    tgemm<false, true, false, false>
        <<<dim3(NP / 128, KVC / 128, BATCH), 256>>>(
            kv_w, x, kv, KVC, NP, CIN, CIN, NP, NP,
            0LL, (long long)CIN * NP, (long long)KVC * NP, sc + 0, bi + 0, 1.0f);

    // q = BN(q_w @ xq), then transpose
    tgemm<false, true, false, false>
        <<<dim3(QP / 128, QC / 128, BATCH), 256>>>(
            q_w, xq, q, QC, QP, CIN, CIN, QP, QP,
            0LL, (long long)CIN * QP, (long long)QC * QP, sc + 1280, bi + 1280, 1.0f);
    qtrans_k<<<(BATCH * HEADS * QP * KD) / 256, 256>>>(q, qT);

    // S = (qT @ k) * scale
    tgemm<false, false, false, true>
        <<<dim3(NP / 128, QP / 128, BATCH * HEADS), 256>>>(
            qT, kv, att, QP, NP, KD, KD, NP, NP,
            (long long)QP * KD, (long long)(KD + VD) * NP, (long long)QP * NP,
            nullptr, nullptr, 0.17677669529663687f);

    softmax_k<<<(BATCH * HEADS * QP) / 8, 256>>>(att);

    // o = gelu(v @ att^T)   (B transposed)
    tgemm<true, false, true, false>
        <<<dim3(QP / 128, VD / 128, BATCH * HEADS), 256>>>(
            kv + (long long)KD * NP, att, o, VD, QP, NP, NP, NP, QP,
            (long long)(KD + VD) * NP, (long long)QP * NP, (long long)VD * QP,
            nullptr, nullptr, 1.0f);

    // mg = BN(mg_w @ o)
    tgemm<false, true, false, false>
        <<<dim3(QP / 128, DOUT / 128, BATCH), 256>>>(
            mg_w, o, mg, DOUT, QP, MERGE, MERGE, QP, QP,
            0LL, (long long)MERGE * QP, (long long)DOUT * QP, sc + 1536, bi + 1536, 1.0f);

    // f1 = gelu(BN(fc1_w @ mg))
    tgemm<false, true, true, false>
        <<<dim3(QP / 128, HID / 128, BATCH), 256>>>(
            fc1_w, mg, f1, HID, QP, DOUT, DOUT, QP, QP,
            0LL, (long long)DOUT * QP, (long long)HID * QP, sc + 2048, bi + 2048, 1.0f);

    // out = BN(fc2_w @ f1)
    tgemm<false, true, false, false>
        <<<dim3(QP / 128, DOUT / 128, BATCH), 256>>>(
            fc2_w, f1, out, DOUT, QP, HID, HID, QP, QP,
            0LL, (long long)HID * QP, (long long)DOUT * QP, sc + 3072, bi + 3072, 1.0f);
}

// round 3
// speedup vs baseline: 2.5079x; 1.2466x over previous
#include <cuda_runtime.h>
#include <math.h>

// ---------------------------------------------------------------------------
// SubSample attention block — tf32 mma.sync + cp.async double-buffered smem.
// f32 staged raw into smem (mma reads top 19 bits as tf32; no cvt pass).
// ---------------------------------------------------------------------------

constexpr int BATCH = 32, CIN = 256, NP = 1024, QP = 256;
constexpr int HEADS = 8, KD = 32, VD = 128;
constexpr int KVC = (KD + VD) * HEADS;   // 1280
constexpr int QC  = HEADS * KD;          // 256
constexpr int MERGE = HEADS * VD;        // 1024
constexpr int DOUT = 512, HID = 1024;

constexpr int AS_STRIDE = 36;            // floats per row, [128][36]
constexpr int BS_STRIDE = 136;           // floats per row, [32][136]
constexpr int AS_ELEMS  = 128 * AS_STRIDE;
constexpr int SMEM_BYTES = 2 * AS_ELEMS * 4 * 2;   // A ring + B ring (worst case) = 73728

__device__ __align__(16) float g_kv [(size_t)BATCH * KVC * NP];
__device__ __align__(16) float g_xq [(size_t)BATCH * CIN * QP];
__device__ __align__(16) float g_q  [(size_t)BATCH * QC  * QP];
__device__ __align__(16) float g_qT [(size_t)BATCH * HEADS * QP * KD];
__device__ __align__(16) float g_att[(size_t)BATCH * HEADS * QP * NP];
__device__ __align__(16) float g_o  [(size_t)BATCH * MERGE * QP];
__device__ __align__(16) float g_mg [(size_t)BATCH * DOUT * QP];
__device__ __align__(16) float g_f1 [(size_t)BATCH * HID  * QP];
__device__ float g_sc[3584];
__device__ float g_bi[3584];

__device__ __forceinline__ float gelu_exact(float x) {
    return 0.5f * x * (1.0f + erff(x * 0.70710678118654752f));
}

__device__ __forceinline__ void cpa16(float* dst, const float* src) {
    unsigned d = (unsigned)__cvta_generic_to_shared(dst);
    asm volatile("cp.async.ca.shared.global [%0], [%1], 16;\n" :: "r"(d), "l"(src));
}
__device__ __forceinline__ void cp_commit() { asm volatile("cp.async.commit_group;\n"); }
template <int W> __device__ __forceinline__ void cp_wait() {
    asm volatile("cp.async.wait_group %0;\n" :: "n"(W));
}

__global__ void affine_prep(const float* __restrict__ g, const float* __restrict__ b,
                            const float* __restrict__ m, const float* __restrict__ v,
                            float* __restrict__ sc, float* __restrict__ bi, int n) {
    int i = blockIdx.x * blockDim.x + threadIdx.x;
    if (i < n) {
        float s = g[i] * rsqrtf(v[i] + 1e-5f);
        sc[i] = s;
        bi[i] = b[i] - m[i] * s;
    }
}

__global__ void subsample_k(const float* __restrict__ x, float* __restrict__ xq) {
    int i = blockIdx.x * 256 + threadIdx.x;
    int qp = i & 255;
    int bc = i >> 8;
    int qy = qp >> 4, qx = qp & 15;
    xq[i] = x[((size_t)bc << 10) + (qy << 6) + (qx << 1)];
}

__global__ void qtrans_k(const float* __restrict__ q, float* __restrict__ qT) {
    int i = blockIdx.x * 256 + threadIdx.x;
    int d  = i & 31;
    int qp = (i >> 5) & 255;
    int z  = i >> 13;
    int b = z >> 3, h = z & 7;
    qT[i] = q[(((size_t)b * QC + h * KD + d) << 8) + qp];
}

__global__ void softmax_k(float* __restrict__ att) {
    int gw   = (blockIdx.x * 256 + threadIdx.x) >> 5;
    int lane = threadIdx.x & 31;
    float4* row = reinterpret_cast<float4*>(att + (size_t)gw * NP);
    float4 v[8];
    float mx = -1e30f;
#pragma unroll
    for (int r = 0; r < 8; r++) {
        v[r] = row[lane + 32 * r];
        mx = fmaxf(mx, fmaxf(fmaxf(v[r].x, v[r].y), fmaxf(v[r].z, v[r].w)));
    }
#pragma unroll
    for (int off = 16; off >= 1; off >>= 1)
        mx = fmaxf(mx, __shfl_xor_sync(0xffffffffu, mx, off));
    float sum = 0.0f;
#pragma unroll
    for (int r = 0; r < 8; r++) {
        v[r].x = __expf(v[r].x - mx); v[r].y = __expf(v[r].y - mx);
        v[r].z = __expf(v[r].z - mx); v[r].w = __expf(v[r].w - mx);
        sum += v[r].x + v[r].y + v[r].z + v[r].w;
    }
#pragma unroll
    for (int off = 16; off >= 1; off >>= 1)
        sum += __shfl_xor_sync(0xffffffffu, sum, off);
    float inv = 1.0f / sum;
#pragma unroll
    for (int r = 0; r < 8; r++) {
        v[r].x *= inv; v[r].y *= inv; v[r].z *= inv; v[r].w *= inv;
        row[lane + 32 * r] = v[r];
    }
}

// ---------------------------------------------------------------------------
// tf32 tensor GEMM, cp.async 2-stage pipeline.
//   BT=false: B stored [k][n], staged into [32][136].
//   BT=true : B stored [n][k], staged into [128][36]; fragments read transposed.
// 128x128 block tile, BK=32, 8 warps (2Mx4N), warp tile 64x32.
// ---------------------------------------------------------------------------
template <bool BT, bool AFF, bool GEL, bool SCL>
__global__ __launch_bounds__(256, 2)
void tgemm(const float* __restrict__ A, const float* __restrict__ B,
           float* __restrict__ C,
           int M, int N, int K, int lda, int ldb, int ldc,
           long long sA, long long sB, long long sC,
           const float* __restrict__ scale, const float* __restrict__ bias,
           float cmul) {
    A += (long long)blockIdx.z * sA;
    B += (long long)blockIdx.z * sB;
    C += (long long)blockIdx.z * sC;
    const int bm = blockIdx.y * 128;
    const int bn = blockIdx.x * 128;

    extern __shared__ float smem[];
    float* As = smem;                       // [2][128*36]
    float* Bs = smem + 2 * AS_ELEMS;        // [2][128*36] (BT) or [2][32*136]

    const int t    = threadIdx.x;
    const int warp = t >> 5, lane = t & 31;
    const int wm   = warp & 1;
    const int wn   = warp >> 1;
    const int quad = lane >> 2, tq = lane & 3;

    // load-index precompute
    const int lr  = t >> 1;                 // 0..127 (row for A / BT-B)
    const int lkc = (t & 1) * 4;            // 0 or 4; +8*j per chunk
    const int n4  = (t & 31) * 4;           // non-BT B: n offset
    const int kr0 = t >> 5;                 // non-BT B: k row base, +8*j

    auto load_tiles = [&](int s, int k0) {
        float* as = As + s * AS_ELEMS;
#pragma unroll
        for (int j = 0; j < 4; j++) {
            int kc = lkc + 8 * j;
            cpa16(as + lr * AS_STRIDE + kc, A + (long long)(bm + lr) * lda + k0 + kc);
        }
        if (BT) {
            float* bs = Bs + s * AS_ELEMS;
#pragma unroll
            for (int j = 0; j < 4; j++) {
                int kc = lkc + 8 * j;
                cpa16(bs + lr * AS_STRIDE + kc, B + (long long)(bn + lr) * ldb + k0 + kc);
            }
        } else {
            float* bs = Bs + s * 32 * BS_STRIDE;
#pragma unroll
            for (int j = 0; j < 4; j++) {
                int kr = kr0 + 8 * j;
                cpa16(bs + kr * BS_STRIDE + n4, B + (long long)(k0 + kr) * ldb + bn + n4);
            }
        }
    };

    float acc[4][4][4];
#pragma unroll
    for (int i = 0; i < 4; i++)
#pragma unroll
        for (int j = 0; j < 4; j++)
#pragma unroll
            for (int r = 0; r < 4; r++) acc[i][j][r] = 0.0f;

    const int niter = K >> 5;
    load_tiles(0, 0);
    cp_commit();

    for (int it = 0; it < niter; it++) {
        const int s = it & 1;
        if (it + 1 < niter) load_tiles(s ^ 1, (it + 1) << 5);
        cp_commit();
        cp_wait<1>();
        __syncthreads();

        const float* as = As + s * AS_ELEMS;
        const float* bs = BT ? (Bs + s * AS_ELEMS) : (Bs + s * 32 * BS_STRIDE);
#pragma unroll
        for (int kk = 0; kk < 4; kk++) {
            const int kb = kk * 8;
            unsigned a[4][4];
#pragma unroll
            for (int mi = 0; mi < 4; mi++) {
                int r = wm * 64 + mi * 16 + quad;
                int c = kb + tq;
                a[mi][0] = __float_as_uint(as[r * AS_STRIDE + c]);
                a[mi][1] = __float_as_uint(as[(r + 8) * AS_STRIDE + c]);
                a[mi][2] = __float_as_uint(as[r * AS_STRIDE + c + 4]);
                a[mi][3] = __float_as_uint(as[(r + 8) * AS_STRIDE + c + 4]);
            }
            unsigned b[4][2];
#pragma unroll
            for (int ni = 0; ni < 4; ni++) {
                int nn = wn * 32 + ni * 8 + quad;
                if (BT) {
                    b[ni][0] = __float_as_uint(bs[nn * AS_STRIDE + kb + tq]);
                    b[ni][1] = __float_as_uint(bs[nn * AS_STRIDE + kb + tq + 4]);
                } else {
                    b[ni][0] = __float_as_uint(bs[(kb + tq) * BS_STRIDE + nn]);
                    b[ni][1] = __float_as_uint(bs[(kb + tq + 4) * BS_STRIDE + nn]);
                }
            }
#pragma unroll
            for (int mi = 0; mi < 4; mi++)
#pragma unroll
                for (int ni = 0; ni < 4; ni++) {
                    asm volatile(
                        "mma.sync.aligned.m16n8k8.row.col.f32.tf32.tf32.f32 "
                        "{%0,%1,%2,%3}, {%4,%5,%6,%7}, {%8,%9}, {%0,%1,%2,%3};"
                        : "+f"(acc[mi][ni][0]), "+f"(acc[mi][ni][1]),
                          "+f"(acc[mi][ni][2]), "+f"(acc[mi][ni][3])
                        : "r"(a[mi][0]), "r"(a[mi][1]), "r"(a[mi][2]), "r"(a[mi][3]),
                          "r"(b[ni][0]), "r"(b[ni][1]));
                }
        }
        __syncthreads();
    }

    // epilogue
#pragma unroll
    for (int mi = 0; mi < 4; mi++) {
        int r0 = bm + wm * 64 + mi * 16 + quad;
        int r1 = r0 + 8;
        float s0 = 1.0f, b0 = 0.0f, s1 = 1.0f, b1 = 0.0f;
        if (AFF) { s0 = scale[r0]; b0 = bias[r0]; s1 = scale[r1]; b1 = bias[r1]; }
#pragma unroll
        for (int ni = 0; ni < 4; ni++) {
            int col = bn + wn * 32 + ni * 8 + 2 * tq;
            float v0 = acc[mi][ni][0], v1 = acc[mi][ni][1];
            float v2 = acc[mi][ni][2], v3 = acc[mi][ni][3];
            if (SCL) { v0 *= cmul; v1 *= cmul; v2 *= cmul; v3 *= cmul; }
            if (AFF) {
                v0 = fmaf(v0, s0, b0); v1 = fmaf(v1, s0, b0);
                v2 = fmaf(v2, s1, b1); v3 = fmaf(v3, s1, b1);
            }
            if (GEL) {
                v0 = gelu_exact(v0); v1 = gelu_exact(v1);
                v2 = gelu_exact(v2); v3 = gelu_exact(v3);
            }
            *reinterpret_cast<float2*>(C + (long long)r0 * ldc + col) = make_float2(v0, v1);
            *reinterpret_cast<float2*>(C + (long long)r1 * ldc + col) = make_float2(v2, v3);
        }
    }
}

// ---------------------------------------------------------------------------
extern "C" void kernel_launch(void* const* d_in, const int* in_sizes, int n_in,
                              void* d_out, int out_size) {
    const float* x     = (const float*)d_in[0];
    const float* kv_w  = (const float*)d_in[1];
    const float* q_w   = (const float*)d_in[6];
    const float* mg_w  = (const float*)d_in[11];
    const float* fc1_w = (const float*)d_in[16];
    const float* fc2_w = (const float*)d_in[21];
    float* out = (float*)d_out;

    float *kv, *xq, *q, *qT, *att, *o, *mg, *f1, *sc, *bi;
    cudaGetSymbolAddress((void**)&kv,  g_kv);
    cudaGetSymbolAddress((void**)&xq,  g_xq);
    cudaGetSymbolAddress((void**)&q,   g_q);
    cudaGetSymbolAddress((void**)&qT,  g_qT);
    cudaGetSymbolAddress((void**)&att, g_att);
    cudaGetSymbolAddress((void**)&o,   g_o);
    cudaGetSymbolAddress((void**)&mg,  g_mg);
    cudaGetSymbolAddress((void**)&f1,  g_f1);
    cudaGetSymbolAddress((void**)&sc,  g_sc);
    cudaGetSymbolAddress((void**)&bi,  g_bi);

    // raise dynamic smem limit for each instantiation (idempotent host calls)
    cudaFuncSetAttribute(tgemm<false, true,  false, false>, cudaFuncAttributeMaxDynamicSharedMemorySize, SMEM_BYTES);
    cudaFuncSetAttribute(tgemm<false, false, false, true >, cudaFuncAttributeMaxDynamicSharedMemorySize, SMEM_BYTES);
    cudaFuncSetAttribute(tgemm<true,  false, true,  false>, cudaFuncAttributeMaxDynamicSharedMemorySize, SMEM_BYTES);
    cudaFuncSetAttribute(tgemm<false, true,  true,  false>, cudaFuncAttributeMaxDynamicSharedMemorySize, SMEM_BYTES);

    affine_prep<<<5, 256>>>((const float*)d_in[2], (const float*)d_in[3],
                            (const float*)d_in[4], (const float*)d_in[5],
                            sc + 0, bi + 0, KVC);
    affine_prep<<<1, 256>>>((const float*)d_in[7], (const float*)d_in[8],
                            (const float*)d_in[9], (const float*)d_in[10],
                            sc + 1280, bi + 1280, QC);
    affine_prep<<<2, 256>>>((const float*)d_in[12], (const float*)d_in[13],
                            (const float*)d_in[14], (const float*)d_in[15],
                            sc + 1536, bi + 1536, DOUT);
    affine_prep<<<4, 256>>>((const float*)d_in[17], (const float*)d_in[18],
                            (const float*)d_in[19], (const float*)d_in[20],
                            sc + 2048, bi + 2048, HID);
    affine_prep<<<2, 256>>>((const float*)d_in[22], (const float*)d_in[23],
                            (const float*)d_in[24], (const float*)d_in[25],
                            sc + 3072, bi + 3072, DOUT);

    subsample_k<<<(BATCH * CIN * QP) / 256, 256>>>(x, xq);

    // kv = BN(kv_w @ x)
    tgemm<false, true, false, false>
        <<<dim3(NP / 128, KVC / 128, BATCH), 256, SMEM_BYTES>>>(
            kv_w, x, kv, KVC, NP, CIN, CIN, NP, NP,
            0LL, (long long)CIN * NP, (long long)KVC * NP, sc + 0, bi + 0, 1.0f);

    // q = BN(q_w @ xq), then transpose
    tgemm<false, true, false, false>
        <<<dim3(QP / 128, QC / 128, BATCH), 256, SMEM_BYTES>>>(
            q_w, xq, q, QC, QP, CIN, CIN, QP, QP,
            0LL, (long long)CIN * QP, (long long)QC * QP, sc + 1280, bi + 1280, 1.0f);
    qtrans_k<<<(BATCH * HEADS * QP * KD) / 256, 256>>>(q, qT);

    // S = (qT @ k) * scale
    tgemm<false, false, false, true>
        <<<dim3(NP / 128, QP / 128, BATCH * HEADS), 256, SMEM_BYTES>>>(
            qT, kv, att, QP, NP, KD, KD, NP, NP,
            (long long)QP * KD, (long long)(KD + VD) * NP, (long long)QP * NP,
            nullptr, nullptr, 0.17677669529663687f);

    softmax_k<<<(BATCH * HEADS * QP) / 8, 256>>>(att);

    // o = gelu(v @ att^T)   (B transposed)
    tgemm<true, false, true, false>
        <<<dim3(QP / 128, VD / 128, BATCH * HEADS), 256, SMEM_BYTES>>>(
            kv + (long long)KD * NP, att, o, VD, QP, NP, NP, NP, QP,
            (long long)(KD + VD) * NP, (long long)QP * NP, (long long)VD * QP,
            nullptr, nullptr, 1.0f);

    // mg = BN(mg_w @ o)
    tgemm<false, true, false, false>
        <<<dim3(QP / 128, DOUT / 128, BATCH), 256, SMEM_BYTES>>>(
            mg_w, o, mg, DOUT, QP, MERGE, MERGE, QP, QP,
            0LL, (long long)MERGE * QP, (long long)DOUT * QP, sc + 1536, bi + 1536, 1.0f);

    // f1 = gelu(BN(fc1_w @ mg))
    tgemm<false, true, true, false>
        <<<dim3(QP / 128, HID / 128, BATCH), 256, SMEM_BYTES>>>(
            fc1_w, mg, f1, HID, QP, DOUT, DOUT, QP, QP,
            0LL, (long long)DOUT * QP, (long long)HID * QP, sc + 2048, bi + 2048, 1.0f);

    // out = BN(fc2_w @ f1)
    tgemm<false, true, false, false>
        <<<dim3(QP / 128, DOUT / 128, BATCH), 256, SMEM_BYTES>>>(
            fc2_w, f1, out, DOUT, QP, HID, HID, QP, QP,
            0LL, (long long)HID * QP, (long long)DOUT * QP, sc + 3072, bi + 3072, 1.0f);
}

// round 4
// speedup vs baseline: 3.1253x; 1.2462x over previous
#include <cuda_runtime.h>
#include <math.h>

// ---------------------------------------------------------------------------
// SubSample attention block — tf32 mma.sync, flash-fused attention core.
//  dense GEMMs (kv, q, mg, fc1, fc2): cp.async double-buffered tf32 tgemm
//  attention (S, softmax, P@V): single fused kernel, online softmax,
//  P held in registers (quad-shuffle fragment conversion), output written
//  transposed (oT[b][q][h*VD+vd]) so mg consumes it via the BT path.
// ---------------------------------------------------------------------------

constexpr int BATCH = 32, CIN = 256, NP = 1024, QP = 256;
constexpr int HEADS = 8, KD = 32, VD = 128;
constexpr int KVC = (KD + VD) * HEADS;   // 1280
constexpr int QC  = HEADS * KD;          // 256
constexpr int MERGE = HEADS * VD;        // 1024
constexpr int DOUT = 512, HID = 1024;

constexpr int AS_STRIDE = 36;
constexpr int BS_STRIDE = 136;
constexpr int AS_ELEMS  = 128 * AS_STRIDE;
constexpr int SMEM_BYTES = 2 * AS_ELEMS * 4 * 2;   // tgemm rings = 73728 B

// flash smem: Qs[128][36] + Ks[2][32][136] + Vs[2][128][132]
constexpr int FL_QS = 128 * 36;
constexpr int FL_KS = 32 * 136;
constexpr int FL_VS = 128 * 132;
constexpr int FL_SMEM_BYTES = (FL_QS + 2 * FL_KS + 2 * FL_VS) * 4;  // 188416

__device__ __align__(16) float g_kv [(size_t)BATCH * KVC * NP];
__device__ __align__(16) float g_xq [(size_t)BATCH * CIN * QP];
__device__ __align__(16) float g_q  [(size_t)BATCH * QC  * QP];
__device__ __align__(16) float g_oT [(size_t)BATCH * QP * MERGE];   // [b][q][merge]
__device__ __align__(16) float g_mg [(size_t)BATCH * DOUT * QP];
__device__ __align__(16) float g_f1 [(size_t)BATCH * HID  * QP];
__device__ float g_sc[3584];
__device__ float g_bi[3584];

__device__ __forceinline__ float gelu_exact(float x) {
    return 0.5f * x * (1.0f + erff(x * 0.70710678118654752f));
}

__device__ __forceinline__ void cpa16(float* dst, const float* src) {
    unsigned d = (unsigned)__cvta_generic_to_shared(dst);
    asm volatile("cp.async.ca.shared.global [%0], [%1], 16;\n" :: "r"(d), "l"(src));
}
__device__ __forceinline__ void cp_commit() { asm volatile("cp.async.commit_group;\n"); }
template <int W> __device__ __forceinline__ void cp_wait() {
    asm volatile("cp.async.wait_group %0;\n" :: "n"(W));
}

__device__ __forceinline__ void mma_tf32(float* c, const unsigned* a, unsigned b0, unsigned b1) {
    asm volatile(
        "mma.sync.aligned.m16n8k8.row.col.f32.tf32.tf32.f32 "
        "{%0,%1,%2,%3}, {%4,%5,%6,%7}, {%8,%9}, {%0,%1,%2,%3};"
        : "+f"(c[0]), "+f"(c[1]), "+f"(c[2]), "+f"(c[3])
        : "r"(a[0]), "r"(a[1]), "r"(a[2]), "r"(a[3]), "r"(b0), "r"(b1));
}

__global__ void affine_prep(const float* __restrict__ g, const float* __restrict__ b,
                            const float* __restrict__ m, const float* __restrict__ v,
                            float* __restrict__ sc, float* __restrict__ bi, int n) {
    int i = blockIdx.x * blockDim.x + threadIdx.x;
    if (i < n) {
        float s = g[i] * rsqrtf(v[i] + 1e-5f);
        sc[i] = s;
        bi[i] = b[i] - m[i] * s;
    }
}

__global__ void subsample_k(const float* __restrict__ x, float* __restrict__ xq) {
    int i = blockIdx.x * 256 + threadIdx.x;
    int qp = i & 255;
    int bc = i >> 8;
    int qy = qp >> 4, qx = qp & 15;
    xq[i] = x[((size_t)bc << 10) + (qy << 6) + (qx << 1)];
}

// ---------------------------------------------------------------------------
// Flash attention: grid (QP/128, BATCH*HEADS), 256 threads (8 warps x 16 q).
// S = (q^T k) * scale (scale folded into Qs), online softmax, o = P @ V^T,
// epilogue: o/l, gelu, store oT[b][q][h*VD+vd].
// ---------------------------------------------------------------------------
__global__ __launch_bounds__(256, 1)
void flash_attn(const float* __restrict__ q, const float* __restrict__ kv,
                float* __restrict__ oT) {
    const int t    = threadIdx.x;
    const int warp = t >> 5, lane = t & 31;
    const int g    = lane >> 2, tq = lane & 3;
    const int bh   = blockIdx.y;
    const int b    = bh >> 3, h = bh & 7;
    const int q0   = blockIdx.x * 128;

    extern __shared__ float sm[];
    float* Qs = sm;                 // [128][36]  rows q, cols d
    float* Ks = Qs + FL_QS;         // [2][32][136] rows d, cols n
    float* Vs = Ks + 2 * FL_KS;     // [2][128][132] rows vd, cols n

    const float* qbase = q  + ((size_t)(b * QC + h * KD) << 8);
    const float* kbase = kv + (size_t)b * KVC * NP + (size_t)(h * (KD + VD)) * NP;
    const float* vbase = kbase + (size_t)KD * NP;

    // stage Q (pre-scaled), transposed [qp][d]
#pragma unroll
    for (int j = 0; j < 4; j++) {
        int idx = j * 256 + t;
        int d = idx >> 5, qp4 = (idx & 31) * 4;
        float4 v = *reinterpret_cast<const float4*>(qbase + ((size_t)d << 8) + q0 + qp4);
        Qs[(qp4 + 0) * 36 + d] = v.x * 0.17677669529663687f;
        Qs[(qp4 + 1) * 36 + d] = v.y * 0.17677669529663687f;
        Qs[(qp4 + 2) * 36 + d] = v.z * 0.17677669529663687f;
        Qs[(qp4 + 3) * 36 + d] = v.w * 0.17677669529663687f;
    }

    auto loadKV = [&](int s, int n0) {
        float* ks = Ks + s * FL_KS;
#pragma unroll
        for (int j = 0; j < 4; j++) {
            int idx = j * 256 + t;
            int d = idx >> 5, c = (idx & 31) * 4;
            cpa16(ks + d * 136 + c, kbase + (size_t)d * NP + n0 + c);
        }
        float* vs = Vs + s * FL_VS;
#pragma unroll
        for (int j = 0; j < 16; j++) {
            int idx = j * 256 + t;
            int vd = idx >> 5, c = (idx & 31) * 4;
            cpa16(vs + vd * 132 + c, vbase + (size_t)vd * NP + n0 + c);
        }
    };

    loadKV(0, 0);
    cp_commit();
    __syncthreads();   // Qs visible

    // Q fragments (constant over key blocks): rows 16*warp+g, +8
    unsigned aq[4][4];
#pragma unroll
    for (int kb = 0; kb < 4; kb++) {
        int r = warp * 16 + g;
        int c = kb * 8 + tq;
        aq[kb][0] = __float_as_uint(Qs[r * 36 + c]);
        aq[kb][1] = __float_as_uint(Qs[(r + 8) * 36 + c]);
        aq[kb][2] = __float_as_uint(Qs[r * 36 + c + 4]);
        aq[kb][3] = __float_as_uint(Qs[(r + 8) * 36 + c + 4]);
    }

    float m0 = -1e30f, m1 = -1e30f, l0 = 0.0f, l1 = 0.0f;
    float o[16][4];
#pragma unroll
    for (int j = 0; j < 16; j++)
#pragma unroll
        for (int r = 0; r < 4; r++) o[j][r] = 0.0f;

    const int srcl0 = (lane & ~3) | (tq >> 1);
    const int srcl1 = srcl0 + 2;
    const bool odd  = (tq & 1);

    for (int blk = 0; blk < 8; blk++) {
        const int s = blk & 1;
        if (blk + 1 < 8) loadKV(s ^ 1, (blk + 1) * 128);
        cp_commit();
        cp_wait<1>();
        __syncthreads();

        const float* ks = Ks + s * FL_KS;
        const float* vs = Vs + s * FL_VS;

        // S tile: C[q16][n8] per ni
        float p[16][4];
#pragma unroll
        for (int ni = 0; ni < 16; ni++) {
            p[ni][0] = p[ni][1] = p[ni][2] = p[ni][3] = 0.0f;
#pragma unroll
            for (int kb = 0; kb < 4; kb++) {
                unsigned b0 = __float_as_uint(ks[(kb * 8 + tq) * 136 + ni * 8 + g]);
                unsigned b1 = __float_as_uint(ks[(kb * 8 + tq + 4) * 136 + ni * 8 + g]);
                mma_tf32(p[ni], aq[kb], b0, b1);
            }
        }

        // online softmax
        float bm0 = -1e30f, bm1 = -1e30f;
#pragma unroll
        for (int ni = 0; ni < 16; ni++) {
            bm0 = fmaxf(bm0, fmaxf(p[ni][0], p[ni][1]));
            bm1 = fmaxf(bm1, fmaxf(p[ni][2], p[ni][3]));
        }
        bm0 = fmaxf(bm0, __shfl_xor_sync(0xffffffffu, bm0, 1));
        bm0 = fmaxf(bm0, __shfl_xor_sync(0xffffffffu, bm0, 2));
        bm1 = fmaxf(bm1, __shfl_xor_sync(0xffffffffu, bm1, 1));
        bm1 = fmaxf(bm1, __shfl_xor_sync(0xffffffffu, bm1, 2));
        float mn0 = fmaxf(m0, bm0), mn1 = fmaxf(m1, bm1);
        float al0 = __expf(m0 - mn0), al1 = __expf(m1 - mn1);
        float rs0 = 0.0f, rs1 = 0.0f;
#pragma unroll
        for (int ni = 0; ni < 16; ni++) {
            p[ni][0] = __expf(p[ni][0] - mn0);
            p[ni][1] = __expf(p[ni][1] - mn0);
            p[ni][2] = __expf(p[ni][2] - mn1);
            p[ni][3] = __expf(p[ni][3] - mn1);
            rs0 += p[ni][0] + p[ni][1];
            rs1 += p[ni][2] + p[ni][3];
        }
        rs0 += __shfl_xor_sync(0xffffffffu, rs0, 1);
        rs0 += __shfl_xor_sync(0xffffffffu, rs0, 2);
        rs1 += __shfl_xor_sync(0xffffffffu, rs1, 1);
        rs1 += __shfl_xor_sync(0xffffffffu, rs1, 2);
        l0 = l0 * al0 + rs0;
        l1 = l1 * al1 + rs1;
        m0 = mn0; m1 = mn1;
#pragma unroll
        for (int j = 0; j < 16; j++) {
            o[j][0] *= al0; o[j][1] *= al0;
            o[j][2] *= al1; o[j][3] *= al1;
        }

        // P @ V : contraction over this block's 128 keys, 8 at a time (ni)
#pragma unroll
        for (int ni = 0; ni < 16; ni++) {
            // convert C-frag (cols 2tq,2tq+1) -> A-frag (cols tq, tq+4)
            float t00 = __shfl_sync(0xffffffffu, p[ni][0], srcl0);
            float t01 = __shfl_sync(0xffffffffu, p[ni][1], srcl0);
            float t10 = __shfl_sync(0xffffffffu, p[ni][2], srcl0);
            float t11 = __shfl_sync(0xffffffffu, p[ni][3], srcl0);
            float t20 = __shfl_sync(0xffffffffu, p[ni][0], srcl1);
            float t21 = __shfl_sync(0xffffffffu, p[ni][1], srcl1);
            float t30 = __shfl_sync(0xffffffffu, p[ni][2], srcl1);
            float t31 = __shfl_sync(0xffffffffu, p[ni][3], srcl1);
            unsigned ap[4];
            ap[0] = __float_as_uint(odd ? t01 : t00);
            ap[1] = __float_as_uint(odd ? t11 : t10);
            ap[2] = __float_as_uint(odd ? t21 : t20);
            ap[3] = __float_as_uint(odd ? t31 : t30);
#pragma unroll
            for (int j = 0; j < 16; j++) {
                unsigned b0 = __float_as_uint(vs[(j * 8 + g) * 132 + ni * 8 + tq]);
                unsigned b1 = __float_as_uint(vs[(j * 8 + g) * 132 + ni * 8 + tq + 4]);
                mma_tf32(o[j], ap, b0, b1);
            }
        }
        __syncthreads();
    }

    // epilogue: normalize, gelu, store transposed
    float inv0 = 1.0f / l0, inv1 = 1.0f / l1;
    int r0 = q0 + warp * 16 + g;
    int r1 = r0 + 8;
    float* orow0 = oT + ((size_t)b * QP + r0) * MERGE + h * VD;
    float* orow1 = oT + ((size_t)b * QP + r1) * MERGE + h * VD;
#pragma unroll
    for (int j = 0; j < 16; j++) {
        int col = j * 8 + 2 * tq;
        float v0 = gelu_exact(o[j][0] * inv0);
        float v1 = gelu_exact(o[j][1] * inv0);
        float v2 = gelu_exact(o[j][2] * inv1);
        float v3 = gelu_exact(o[j][3] * inv1);
        *reinterpret_cast<float2*>(orow0 + col) = make_float2(v0, v1);
        *reinterpret_cast<float2*>(orow1 + col) = make_float2(v2, v3);
    }
}

// ---------------------------------------------------------------------------
// tf32 tensor GEMM, cp.async 2-stage (unchanged from round 3).
// ---------------------------------------------------------------------------
template <bool BT, bool AFF, bool GEL, bool SCL>
__global__ __launch_bounds__(256, 2)
void tgemm(const float* __restrict__ A, const float* __restrict__ B,
           float* __restrict__ C,
           int M, int N, int K, int lda, int ldb, int ldc,
           long long sA, long long sB, long long sC,
           const float* __restrict__ scale, const float* __restrict__ bias,
           float cmul) {
    A += (long long)blockIdx.z * sA;
    B += (long long)blockIdx.z * sB;
    C += (long long)blockIdx.z * sC;
    const int bm = blockIdx.y * 128;
    const int bn = blockIdx.x * 128;

    extern __shared__ float smem[];
    float* As = smem;
    float* Bs = smem + 2 * AS_ELEMS;

    const int t    = threadIdx.x;
    const int warp = t >> 5, lane = t & 31;
    const int wm   = warp & 1;
    const int wn   = warp >> 1;
    const int quad = lane >> 2, tq = lane & 3;

    const int lr  = t >> 1;
    const int lkc = (t & 1) * 4;
    const int n4  = (t & 31) * 4;
    const int kr0 = t >> 5;

    auto load_tiles = [&](int s, int k0) {
        float* as = As + s * AS_ELEMS;
#pragma unroll
        for (int j = 0; j < 4; j++) {
            int kc = lkc + 8 * j;
            cpa16(as + lr * AS_STRIDE + kc, A + (long long)(bm + lr) * lda + k0 + kc);
        }
        if (BT) {
            float* bs = Bs + s * AS_ELEMS;
#pragma unroll
            for (int j = 0; j < 4; j++) {
                int kc = lkc + 8 * j;
                cpa16(bs + lr * AS_STRIDE + kc, B + (long long)(bn + lr) * ldb + k0 + kc);
            }
        } else {
            float* bs = Bs + s * 32 * BS_STRIDE;
#pragma unroll
            for (int j = 0; j < 4; j++) {
                int kr = kr0 + 8 * j;
                cpa16(bs + kr * BS_STRIDE + n4, B + (long long)(k0 + kr) * ldb + bn + n4);
            }
        }
    };

    float acc[4][4][4];
#pragma unroll
    for (int i = 0; i < 4; i++)
#pragma unroll
        for (int j = 0; j < 4; j++)
#pragma unroll
            for (int r = 0; r < 4; r++) acc[i][j][r] = 0.0f;

    const int niter = K >> 5;
    load_tiles(0, 0);
    cp_commit();

    for (int it = 0; it < niter; it++) {
        const int s = it & 1;
        if (it + 1 < niter) load_tiles(s ^ 1, (it + 1) << 5);
        cp_commit();
        cp_wait<1>();
        __syncthreads();

        const float* as = As + s * AS_ELEMS;
        const float* bs = BT ? (Bs + s * AS_ELEMS) : (Bs + s * 32 * BS_STRIDE);
#pragma unroll
        for (int kk = 0; kk < 4; kk++) {
            const int kb = kk * 8;
            unsigned a[4][4];
#pragma unroll
            for (int mi = 0; mi < 4; mi++) {
                int r = wm * 64 + mi * 16 + quad;
                int c = kb + tq;
                a[mi][0] = __float_as_uint(as[r * AS_STRIDE + c]);
                a[mi][1] = __float_as_uint(as[(r + 8) * AS_STRIDE + c]);
                a[mi][2] = __float_as_uint(as[r * AS_STRIDE + c + 4]);
                a[mi][3] = __float_as_uint(as[(r + 8) * AS_STRIDE + c + 4]);
            }
            unsigned b[4][2];
#pragma unroll
            for (int ni = 0; ni < 4; ni++) {
                int nn = wn * 32 + ni * 8 + quad;
                if (BT) {
                    b[ni][0] = __float_as_uint(bs[nn * AS_STRIDE + kb + tq]);
                    b[ni][1] = __float_as_uint(bs[nn * AS_STRIDE + kb + tq + 4]);
                } else {
                    b[ni][0] = __float_as_uint(bs[(kb + tq) * BS_STRIDE + nn]);
                    b[ni][1] = __float_as_uint(bs[(kb + tq + 4) * BS_STRIDE + nn]);
                }
            }
#pragma unroll
            for (int mi = 0; mi < 4; mi++)
#pragma unroll
                for (int ni = 0; ni < 4; ni++)
                    mma_tf32(acc[mi][ni], a[mi], b[ni][0], b[ni][1]);
        }
        __syncthreads();
    }

#pragma unroll
    for (int mi = 0; mi < 4; mi++) {
        int r0 = bm + wm * 64 + mi * 16 + quad;
        int r1 = r0 + 8;
        float s0 = 1.0f, b0 = 0.0f, s1 = 1.0f, b1 = 0.0f;
        if (AFF) { s0 = scale[r0]; b0 = bias[r0]; s1 = scale[r1]; b1 = bias[r1]; }
#pragma unroll
        for (int ni = 0; ni < 4; ni++) {
            int col = bn + wn * 32 + ni * 8 + 2 * tq;
            float v0 = acc[mi][ni][0], v1 = acc[mi][ni][1];
            float v2 = acc[mi][ni][2], v3 = acc[mi][ni][3];
            if (SCL) { v0 *= cmul; v1 *= cmul; v2 *= cmul; v3 *= cmul; }
            if (AFF) {
                v0 = fmaf(v0, s0, b0); v1 = fmaf(v1, s0, b0);
                v2 = fmaf(v2, s1, b1); v3 = fmaf(v3, s1, b1);
            }
            if (GEL) {
                v0 = gelu_exact(v0); v1 = gelu_exact(v1);
                v2 = gelu_exact(v2); v3 = gelu_exact(v3);
            }
            *reinterpret_cast<float2*>(C + (long long)r0 * ldc + col) = make_float2(v0, v1);
            *reinterpret_cast<float2*>(C + (long long)r1 * ldc + col) = make_float2(v2, v3);
        }
    }
}

// ---------------------------------------------------------------------------
extern "C" void kernel_launch(void* const* d_in, const int* in_sizes, int n_in,
                              void* d_out, int out_size) {
    const float* x     = (const float*)d_in[0];
    const float* kv_w  = (const float*)d_in[1];
    const float* q_w   = (const float*)d_in[6];
    const float* mg_w  = (const float*)d_in[11];
    const float* fc1_w = (const float*)d_in[16];
    const float* fc2_w = (const float*)d_in[21];
    float* out = (float*)d_out;

    float *kv, *xq, *q, *oT, *mg, *f1, *sc, *bi;
    cudaGetSymbolAddress((void**)&kv,  g_kv);
    cudaGetSymbolAddress((void**)&xq,  g_xq);
    cudaGetSymbolAddress((void**)&q,   g_q);
    cudaGetSymbolAddress((void**)&oT,  g_oT);
    cudaGetSymbolAddress((void**)&mg,  g_mg);
    cudaGetSymbolAddress((void**)&f1,  g_f1);
    cudaGetSymbolAddress((void**)&sc,  g_sc);
    cudaGetSymbolAddress((void**)&bi,  g_bi);

    cudaFuncSetAttribute(tgemm<false, true,  false, false>, cudaFuncAttributeMaxDynamicSharedMemorySize, SMEM_BYTES);
    cudaFuncSetAttribute(tgemm<true,  true,  false, false>, cudaFuncAttributeMaxDynamicSharedMemorySize, SMEM_BYTES);
    cudaFuncSetAttribute(tgemm<false, true,  true,  false>, cudaFuncAttributeMaxDynamicSharedMemorySize, SMEM_BYTES);
    cudaFuncSetAttribute(flash_attn, cudaFuncAttributeMaxDynamicSharedMemorySize, FL_SMEM_BYTES);

    affine_prep<<<5, 256>>>((const float*)d_in[2], (const float*)d_in[3],
                            (const float*)d_in[4], (const float*)d_in[5],
                            sc + 0, bi + 0, KVC);
    affine_prep<<<1, 256>>>((const float*)d_in[7], (const float*)d_in[8],
                            (const float*)d_in[9], (const float*)d_in[10],
                            sc + 1280, bi + 1280, QC);
    affine_prep<<<2, 256>>>((const float*)d_in[12], (const float*)d_in[13],
                            (const float*)d_in[14], (const float*)d_in[15],
                            sc + 1536, bi + 1536, DOUT);
    affine_prep<<<4, 256>>>((const float*)d_in[17], (const float*)d_in[18],
                            (const float*)d_in[19], (const float*)d_in[20],
                            sc + 2048, bi + 2048, HID);
    affine_prep<<<2, 256>>>((const float*)d_in[22], (const float*)d_in[23],
                            (const float*)d_in[24], (const float*)d_in[25],
                            sc + 3072, bi + 3072, DOUT);

    subsample_k<<<(BATCH * CIN * QP) / 256, 256>>>(x, xq);

    // kv = BN(kv_w @ x)
    tgemm<false, true, false, false>
        <<<dim3(NP / 128, KVC / 128, BATCH), 256, SMEM_BYTES>>>(
            kv_w, x, kv, KVC, NP, CIN, CIN, NP, NP,
            0LL, (long long)CIN * NP, (long long)KVC * NP, sc + 0, bi + 0, 1.0f);

    // q = BN(q_w @ xq)
    tgemm<false, true, false, false>
        <<<dim3(QP / 128, QC / 128, BATCH), 256, SMEM_BYTES>>>(
            q_w, xq, q, QC, QP, CIN, CIN, QP, QP,
            0LL, (long long)CIN * QP, (long long)QC * QP, sc + 1280, bi + 1280, 1.0f);

    // fused attention: S, softmax, P@V, gelu -> oT[b][q][merge]
    flash_attn<<<dim3(QP / 128, BATCH * HEADS), 256, FL_SMEM_BYTES>>>(q, kv, oT);

    // mg = BN(mg_w @ o) with o given transposed: BT path
    tgemm<true, true, false, false>
        <<<dim3(QP / 128, DOUT / 128, BATCH), 256, SMEM_BYTES>>>(
            mg_w, oT, mg, DOUT, QP, MERGE, MERGE, MERGE, QP,
            0LL, (long long)QP * MERGE, (long long)DOUT * QP, sc + 1536, bi + 1536, 1.0f);

    // f1 = gelu(BN(fc1_w @ mg))
    tgemm<false, true, true, false>
        <<<dim3(QP / 128, HID / 128, BATCH), 256, SMEM_BYTES>>>(
            fc1_w, mg, f1, HID, QP, DOUT, DOUT, QP, QP,
            0LL, (long long)DOUT * QP, (long long)HID * QP, sc + 2048, bi + 2048, 1.0f);

    // out = BN(fc2_w @ f1)
    tgemm<false, true, false, false>
        <<<dim3(QP / 128, DOUT / 128, BATCH), 256, SMEM_BYTES>>>(
            fc2_w, f1, out, DOUT, QP, HID, HID, QP, QP,
            0LL, (long long)HID * QP, (long long)DOUT * QP, sc + 3072, bi + 3072, 1.0f);
}

// round 6
// speedup vs baseline: 5.9105x; 1.8911x over previous
#include <cuda_runtime.h>
#include <cuda_fp16.h>
#include <math.h>
#include <stdint.h>

// ---------------------------------------------------------------------------
// SubSample attention block — fp16 mma.sync (m16n8k16), position-major.
//   xT  = f16(transpose(x))        [b][1024][256]
//   xqT = f16(subsample+transpose) [b][256][256]
//   kv  = f16(BN(xT @ kv_w^T))     [b][1024][1280]
//   q   = f16(BN(xqT@q_w^T)*scl)   [b][256][256]
//   flash: S,softmax,P@V,gelu ->   oT f16 [b][256][1024]
//   mg  = f16(BN(oT @ mg_w^T))     [b][256][512]
//   f1  = f16(gelu(BN(mg@fc1^T)))  [b][256][1024]
//   out = BN(f1 @ fc2^T)^T  f32    [b][512][256]  (smem-bounce transpose)
// All mma: m16n8k16 f16 inputs, f32 accumulate.
// ---------------------------------------------------------------------------

constexpr int BATCH = 32, CIN = 256, NP = 1024, QP = 256;
constexpr int HEADS = 8, KD = 32, VD = 128;
constexpr int KVC = (KD + VD) * HEADS;   // 1280
constexpr int QC  = HEADS * KD;          // 256
constexpr int MERGE = HEADS * VD;        // 1024
constexpr int DOUT = 512, HID = 1024;

// gemm_h smem: As[2][128*72] + Bs[2][128*72] halves = 73728 B
constexpr int HS_STAGE = 128 * 72;                 // halves per stage per operand
constexpr int GH_SMEM_BYTES = 4 * HS_STAGE * 2;    // 73728

// flash smem (halves): Qs[128][40] + Ks[2][128][40] + Vs[2][128][136]
constexpr int FL_QS = 128 * 40;
constexpr int FL_KS = 128 * 40;
constexpr int FL_VS = 128 * 136;
constexpr int FL_SMEM_BYTES = (FL_QS + 2 * FL_KS + 2 * FL_VS) * 2;  // 100352

__device__ __align__(16) __half g_x16T [(size_t)BATCH * NP * CIN];
__device__ __align__(16) __half g_xq16T[(size_t)BATCH * QP * CIN];
__device__ __align__(16) __half g_kv16 [(size_t)BATCH * NP * KVC];
__device__ __align__(16) __half g_q16  [(size_t)BATCH * QP * QC];
__device__ __align__(16) __half g_oT16 [(size_t)BATCH * QP * MERGE];
__device__ __align__(16) __half g_mg16 [(size_t)BATCH * QP * DOUT];
__device__ __align__(16) __half g_f116 [(size_t)BATCH * QP * HID];
__device__ __align__(16) __half g_kvw16 [KVC * CIN];
__device__ __align__(16) __half g_qw16  [QC * CIN];
__device__ __align__(16) __half g_mgw16 [DOUT * MERGE];
__device__ __align__(16) __half g_fc1w16[HID * DOUT];
__device__ __align__(16) __half g_fc2w16[DOUT * HID];
__device__ float g_sc[3584];
__device__ float g_bi[3584];

__device__ __forceinline__ float gelu_exact(float x) {
    return 0.5f * x * (1.0f + erff(x * 0.70710678118654752f));
}

__device__ __forceinline__ void cpa16(void* dst, const void* src) {
    unsigned d = (unsigned)__cvta_generic_to_shared(dst);
    asm volatile("cp.async.ca.shared.global [%0], [%1], 16;\n" :: "r"(d), "l"(src));
}
__device__ __forceinline__ void cp_commit() { asm volatile("cp.async.commit_group;\n"); }
template <int W> __device__ __forceinline__ void cp_wait() {
    asm volatile("cp.async.wait_group %0;\n" :: "n"(W));
}

__device__ __forceinline__ void mma_f16(float* c, const unsigned* a, unsigned b0, unsigned b1) {
    asm volatile(
        "mma.sync.aligned.m16n8k16.row.col.f32.f16.f16.f32 "
        "{%0,%1,%2,%3}, {%4,%5,%6,%7}, {%8,%9}, {%0,%1,%2,%3};"
        : "+f"(c[0]), "+f"(c[1]), "+f"(c[2]), "+f"(c[3])
        : "r"(a[0]), "r"(a[1]), "r"(a[2]), "r"(a[3]), "r"(b0), "r"(b1));
}

__device__ __forceinline__ void ldsm_t4(unsigned& r0, unsigned& r1, unsigned& r2,
                                        unsigned& r3, unsigned addr) {
    asm volatile("ldmatrix.sync.aligned.m8n8.x4.trans.shared.b16 {%0,%1,%2,%3}, [%4];"
                 : "=r"(r0), "=r"(r1), "=r"(r2), "=r"(r3) : "r"(addr));
}

__device__ __forceinline__ unsigned packh2(float a, float b) {
    __half2 h = __floats2half2_rn(a, b);
    return *reinterpret_cast<unsigned*>(&h);
}
__device__ __forceinline__ unsigned ldu32(const __half* p) {
    return *reinterpret_cast<const unsigned*>(p);
}

// ---------------------------------------------------------------------------
__global__ void affine_prep(const float* __restrict__ g, const float* __restrict__ b,
                            const float* __restrict__ m, const float* __restrict__ v,
                            float* __restrict__ sc, float* __restrict__ bi,
                            int n, float mul) {
    int i = blockIdx.x * blockDim.x + threadIdx.x;
    if (i < n) {
        float s = g[i] * rsqrtf(v[i] + 1e-5f);
        sc[i] = s * mul;
        bi[i] = (b[i] - m[i] * s) * mul;
    }
}

__global__ void cvt16_k(const float* __restrict__ src, __half* __restrict__ dst, int n) {
    int i = blockIdx.x * 256 + threadIdx.x;
    if (i < n) dst[i] = __float2half_rn(src[i]);
}

// x [b][256][1024] f32 -> xT [b][1024][256] f16
__global__ void xtrans_k(const float* __restrict__ x, __half* __restrict__ xT) {
    __shared__ float tile[32][33];
    int b = blockIdx.z;
    int hw0 = blockIdx.x * 32, c0 = blockIdx.y * 32;
    int tx = threadIdx.x, ty = threadIdx.y;
#pragma unroll
    for (int j = 0; j < 4; j++)
        tile[ty + 8 * j][tx] = x[((size_t)(b * CIN + c0 + ty + 8 * j) << 10) + hw0 + tx];
    __syncthreads();
#pragma unroll
    for (int j = 0; j < 4; j++)
        xT[((size_t)b * NP + hw0 + ty + 8 * j) * CIN + c0 + tx] =
            __float2half_rn(tile[tx][ty + 8 * j]);
}

// xqT [b][qp][c] f16, qp=qy*16+qx <- x[b][c][qy*64+qx*2]
__global__ void xq_trans_k(const float* __restrict__ x, __half* __restrict__ xqT) {
    __shared__ float tile[32][33];
    int b = blockIdx.z;
    int qp0 = blockIdx.x * 32, c0 = blockIdx.y * 32;
    int tx = threadIdx.x, ty = threadIdx.y;
    int qp = qp0 + tx;
    int hw = ((qp >> 4) << 6) + ((qp & 15) << 1);
#pragma unroll
    for (int j = 0; j < 4; j++)
        tile[ty + 8 * j][tx] = x[((size_t)(b * CIN + c0 + ty + 8 * j) << 10) + hw];
    __syncthreads();
#pragma unroll
    for (int j = 0; j < 4; j++)
        xqT[((size_t)b * QP + qp0 + ty + 8 * j) * CIN + c0 + tx] =
            __float2half_rn(tile[tx][ty + 8 * j]);
}

// ---------------------------------------------------------------------------
// fp16 GEMM: D[b][m][n] = A[b][m][k] @ W[n][k]^T, both K-major f16.
// 128x128 block, BK=64, 8 warps (2Mx4N), warp tile 64x32, m16n8k16.
// Epilogue: per-column affine (+gelu); HOUT: f16 store; TRANS: f32 transposed.
// ---------------------------------------------------------------------------
template <bool GEL, bool TRANS>
__global__ __launch_bounds__(256, 2)
void gemm_h(const __half* __restrict__ A, const __half* __restrict__ B,
            void* __restrict__ Cv,
            int K, int ldc, long long sA, long long sC,
            const float* __restrict__ scale, const float* __restrict__ bias) {
    extern __shared__ __half smh[];
    __half* As = smh;
    __half* Bs = smh + 2 * HS_STAGE;

    const int t = threadIdx.x, warp = t >> 5, lane = t & 31;
    const int wm = warp & 1, wn = warp >> 1;
    const int g = lane >> 2, tq = lane & 3;
    const int bm = blockIdx.y * 128, bn = blockIdx.x * 128;

    const __half* Ab = A + (long long)blockIdx.z * sA + (long long)bm * K;
    const __half* Bb = B + (long long)bn * K;

    const int lr = t >> 3;          // 0..31? no: 256 threads, idx>>3 below
    const int lc = t & 7;

    auto ldtile = [&](int s, int k0) {
#pragma unroll
        for (int j = 0; j < 4; j++) {
            int idx = j * 256 + t;
            int r = idx >> 3, c = idx & 7;
            cpa16(As + s * HS_STAGE + r * 72 + c * 8, Ab + (long long)r * K + k0 + c * 8);
            cpa16(Bs + s * HS_STAGE + r * 72 + c * 8, Bb + (long long)r * K + k0 + c * 8);
        }
    };
    (void)lr; (void)lc;

    float acc[4][4][4];
#pragma unroll
    for (int i = 0; i < 4; i++)
#pragma unroll
        for (int j = 0; j < 4; j++)
#pragma unroll
            for (int r = 0; r < 4; r++) acc[i][j][r] = 0.0f;

    const int niter = K >> 6;
    ldtile(0, 0);
    cp_commit();

    for (int it = 0; it < niter; it++) {
        const int s = it & 1;
        if (it + 1 < niter) ldtile(s ^ 1, (it + 1) << 6);
        cp_commit();
        cp_wait<1>();
        __syncthreads();

        const __half* as = As + s * HS_STAGE;
        const __half* bs = Bs + s * HS_STAGE;
#pragma unroll
        for (int kb = 0; kb < 4; kb++) {
            const int ko = kb * 16;
            unsigned a[4][4];
#pragma unroll
            for (int mi = 0; mi < 4; mi++) {
                int r = wm * 64 + mi * 16 + g;
                a[mi][0] = ldu32(as + r * 72 + ko + 2 * tq);
                a[mi][1] = ldu32(as + (r + 8) * 72 + ko + 2 * tq);
                a[mi][2] = ldu32(as + r * 72 + ko + 2 * tq + 8);
                a[mi][3] = ldu32(as + (r + 8) * 72 + ko + 2 * tq + 8);
            }
            unsigned b[4][2];
#pragma unroll
            for (int ni = 0; ni < 4; ni++) {
                int nn = wn * 32 + ni * 8 + g;
                b[ni][0] = ldu32(bs + nn * 72 + ko + 2 * tq);
                b[ni][1] = ldu32(bs + nn * 72 + ko + 2 * tq + 8);
            }
#pragma unroll
            for (int mi = 0; mi < 4; mi++)
#pragma unroll
                for (int ni = 0; ni < 4; ni++)
                    mma_f16(acc[mi][ni], a[mi], b[ni][0], b[ni][1]);
        }
        __syncthreads();
    }

    if (!TRANS) {
        __half* Cb = reinterpret_cast<__half*>(Cv) + (long long)blockIdx.z * sC;
#pragma unroll
        for (int mi = 0; mi < 4; mi++) {
            int r0 = bm + wm * 64 + mi * 16 + g;
            int r1 = r0 + 8;
#pragma unroll
            for (int ni = 0; ni < 4; ni++) {
                int col = bn + wn * 32 + ni * 8 + 2 * tq;
                float s0 = scale[col], b0s = bias[col];
                float s1 = scale[col + 1], b1s = bias[col + 1];
                float v0 = fmaf(acc[mi][ni][0], s0, b0s);
                float v1 = fmaf(acc[mi][ni][1], s1, b1s);
                float v2 = fmaf(acc[mi][ni][2], s0, b0s);
                float v3 = fmaf(acc[mi][ni][3], s1, b1s);
                if (GEL) {
                    v0 = gelu_exact(v0); v1 = gelu_exact(v1);
                    v2 = gelu_exact(v2); v3 = gelu_exact(v3);
                }
                *reinterpret_cast<unsigned*>(Cb + (long long)r0 * ldc + col) = packh2(v0, v1);
                *reinterpret_cast<unsigned*>(Cb + (long long)r1 * ldc + col) = packh2(v2, v3);
            }
        }
    } else {
        // transposed f32 epilogue: bounce through smem (reuse tile memory)
        float* Cs = reinterpret_cast<float*>(smh);   // [128][133]
        __syncthreads();
#pragma unroll
        for (int mi = 0; mi < 4; mi++) {
            int r0 = wm * 64 + mi * 16 + g;
            int r1 = r0 + 8;
#pragma unroll
            for (int ni = 0; ni < 4; ni++) {
                int col = wn * 32 + ni * 8 + 2 * tq;
                int cg = bn + col;
                float s0 = scale[cg], b0s = bias[cg];
                float s1 = scale[cg + 1], b1s = bias[cg + 1];
                Cs[r0 * 133 + col]     = fmaf(acc[mi][ni][0], s0, b0s);
                Cs[r0 * 133 + col + 1] = fmaf(acc[mi][ni][1], s1, b1s);
                Cs[r1 * 133 + col]     = fmaf(acc[mi][ni][2], s0, b0s);
                Cs[r1 * 133 + col + 1] = fmaf(acc[mi][ni][3], s1, b1s);
            }
        }
        __syncthreads();
        float* Cb = reinterpret_cast<float*>(Cv) + (long long)blockIdx.z * sC;
        int n = t >> 1;
        int m0 = (t & 1) * 64;
        float* orow = Cb + (long long)(bn + n) * ldc + bm + m0;
#pragma unroll
        for (int i = 0; i < 16; i++) {
            float4 v;
            v.x = Cs[(m0 + i * 4 + 0) * 133 + n];
            v.y = Cs[(m0 + i * 4 + 1) * 133 + n];
            v.z = Cs[(m0 + i * 4 + 2) * 133 + n];
            v.w = Cs[(m0 + i * 4 + 3) * 133 + n];
            *reinterpret_cast<float4*>(orow + i * 4) = v;
        }
    }
}

// ---------------------------------------------------------------------------
// Flash attention fp16: q16 [b][qp][256], kv16 [b][n][1280] (h*160: K 32, V 128)
// out oT16[b][qp][h*128+vd] with gelu.
// ---------------------------------------------------------------------------
__global__ __launch_bounds__(256, 1)
void flash_attn(const __half* __restrict__ q, const __half* __restrict__ kv,
                __half* __restrict__ oT) {
    const int t    = threadIdx.x;
    const int warp = t >> 5, lane = t & 31;
    const int g    = lane >> 2, tq = lane & 3;
    const int bh   = blockIdx.y;
    const int b    = bh >> 3, h = bh & 7;
    const int q0   = blockIdx.x * 128;

    extern __shared__ __half smh[];
    __half* Qs = smh;               // [128 qp][40]  cols d
    __half* Ks = Qs + FL_QS;        // [2][128 n][40] cols d
    __half* Vs = Ks + 2 * FL_KS;    // [2][128 n][136] cols vd

    const __half* kvb = kv + (size_t)b * NP * KVC + h * (KD + VD);

    auto loadKV = [&](int s, int n0) {
        __half* ks = Ks + s * FL_KS;
#pragma unroll
        for (int j = 0; j < 2; j++) {
            int idx = j * 256 + t;
            int n = idx >> 2, c = idx & 3;
            cpa16(ks + n * 40 + c * 8, kvb + (size_t)(n0 + n) * KVC + c * 8);
        }
        __half* vs = Vs + s * FL_VS;
#pragma unroll
        for (int j = 0; j < 8; j++) {
            int idx = j * 256 + t;
            int n = idx >> 4, c = idx & 15;
            cpa16(vs + n * 136 + c * 8, kvb + (size_t)(n0 + n) * KVC + KD + c * 8);
        }
    };

    // stage Q
#pragma unroll
    for (int j = 0; j < 2; j++) {
        int idx = j * 256 + t;
        int r = idx >> 2, c = idx & 3;
        cpa16(Qs + r * 40 + c * 8, q + ((size_t)b * QP + q0 + r) * QC + h * KD + c * 8);
    }
    loadKV(0, 0);
    cp_commit();

    unsigned aq[2][4];
    float m0 = -1e30f, m1 = -1e30f, l0 = 0.0f, l1 = 0.0f;
    float o[16][4];
#pragma unroll
    for (int j = 0; j < 16; j++)
#pragma unroll
        for (int r = 0; r < 4; r++) o[j][r] = 0.0f;

    // ldmatrix per-thread row address (constant part), halves
    const int lmi = lane >> 3, lrow = lane & 7;
    const int ldrow = ((lmi & 1) * 8 + lrow) * 136 + (lmi >> 1) * 8;

    for (int blk = 0; blk < 8; blk++) {
        const int s = blk & 1;
        if (blk + 1 < 8) loadKV(s ^ 1, (blk + 1) * 128);
        cp_commit();
        cp_wait<1>();
        __syncthreads();

        if (blk == 0) {
#pragma unroll
            for (int kb = 0; kb < 2; kb++) {
                int r = warp * 16 + g;
                aq[kb][0] = ldu32(Qs + r * 40 + kb * 16 + 2 * tq);
                aq[kb][1] = ldu32(Qs + (r + 8) * 40 + kb * 16 + 2 * tq);
                aq[kb][2] = ldu32(Qs + r * 40 + kb * 16 + 2 * tq + 8);
                aq[kb][3] = ldu32(Qs + (r + 8) * 40 + kb * 16 + 2 * tq + 8);
            }
        }

        const __half* ks = Ks + s * FL_KS;
        unsigned vs_u32;
        {
            const __half* vsp = Vs + s * FL_VS;
            asm("{ .reg .u64 tmp; cvta.to.shared.u64 tmp, %1; cvt.u32.u64 %0, tmp; }"
                : "=r"(vs_u32) : "l"(vsp));
        }

        // S = Q @ K^T
        float p[16][4];
#pragma unroll
        for (int ni = 0; ni < 16; ni++) {
            p[ni][0] = p[ni][1] = p[ni][2] = p[ni][3] = 0.0f;
            int nn = ni * 8 + g;
#pragma unroll
            for (int kb = 0; kb < 2; kb++) {
                unsigned b0 = ldu32(ks + nn * 40 + kb * 16 + 2 * tq);
                unsigned b1 = ldu32(ks + nn * 40 + kb * 16 + 2 * tq + 8);
                mma_f16(p[ni], aq[kb], b0, b1);
            }
        }

        // online softmax
        float bm0 = -1e30f, bm1 = -1e30f;
#pragma unroll
        for (int ni = 0; ni < 16; ni++) {
            bm0 = fmaxf(bm0, fmaxf(p[ni][0], p[ni][1]));
            bm1 = fmaxf(bm1, fmaxf(p[ni][2], p[ni][3]));
        }
        bm0 = fmaxf(bm0, __shfl_xor_sync(0xffffffffu, bm0, 1));
        bm0 = fmaxf(bm0, __shfl_xor_sync(0xffffffffu, bm0, 2));
        bm1 = fmaxf(bm1, __shfl_xor_sync(0xffffffffu, bm1, 1));
        bm1 = fmaxf(bm1, __shfl_xor_sync(0xffffffffu, bm1, 2));
        float mn0 = fmaxf(m0, bm0), mn1 = fmaxf(m1, bm1);
        float al0 = __expf(m0 - mn0), al1 = __expf(m1 - mn1);
        float rs0 = 0.0f, rs1 = 0.0f;
#pragma unroll
        for (int ni = 0; ni < 16; ni++) {
            p[ni][0] = __expf(p[ni][0] - mn0);
            p[ni][1] = __expf(p[ni][1] - mn0);
            p[ni][2] = __expf(p[ni][2] - mn1);
            p[ni][3] = __expf(p[ni][3] - mn1);
            rs0 += p[ni][0] + p[ni][1];
            rs1 += p[ni][2] + p[ni][3];
        }
        rs0 += __shfl_xor_sync(0xffffffffu, rs0, 1);
        rs0 += __shfl_xor_sync(0xffffffffu, rs0, 2);
        rs1 += __shfl_xor_sync(0xffffffffu, rs1, 1);
        rs1 += __shfl_xor_sync(0xffffffffu, rs1, 2);
        l0 = l0 * al0 + rs0;
        l1 = l1 * al1 + rs1;
        m0 = mn0; m1 = mn1;
#pragma unroll
        for (int j = 0; j < 16; j++) {
            o[j][0] *= al0; o[j][1] *= al0;
            o[j][2] *= al1; o[j][3] *= al1;
        }

        // P @ V : 8 k-steps of 16 keys; A-frag = packed P (no shuffles)
#pragma unroll
        for (int ki = 0; ki < 8; ki++) {
            unsigned ap[4];
            ap[0] = packh2(p[2 * ki][0],     p[2 * ki][1]);
            ap[1] = packh2(p[2 * ki][2],     p[2 * ki][3]);
            ap[2] = packh2(p[2 * ki + 1][0], p[2 * ki + 1][1]);
            ap[3] = packh2(p[2 * ki + 1][2], p[2 * ki + 1][3]);
#pragma unroll
            for (int jj = 0; jj < 8; jj++) {
                unsigned r0, r1, r2, r3;
                ldsm_t4(r0, r1, r2, r3,
                        vs_u32 + 2u * (unsigned)(ki * 16 * 136 + jj * 16 + ldrow));
                mma_f16(o[2 * jj],     ap, r0, r1);
                mma_f16(o[2 * jj + 1], ap, r2, r3);
            }
        }
        __syncthreads();
    }

    // epilogue: normalize, gelu, f16 store
    float inv0 = 1.0f / l0, inv1 = 1.0f / l1;
    int r0 = q0 + warp * 16 + g;
    int r1 = r0 + 8;
    __half* orow0 = oT + ((size_t)b * QP + r0) * MERGE + h * VD;
    __half* orow1 = oT + ((size_t)b * QP + r1) * MERGE + h * VD;
#pragma unroll
    for (int j = 0; j < 16; j++) {
        int col = j * 8 + 2 * tq;
        float v0 = gelu_exact(o[j][0] * inv0);
        float v1 = gelu_exact(o[j][1] * inv0);
        float v2 = gelu_exact(o[j][2] * inv1);
        float v3 = gelu_exact(o[j][3] * inv1);
        *reinterpret_cast<unsigned*>(orow0 + col) = packh2(v0, v1);
        *reinterpret_cast<unsigned*>(orow1 + col) = packh2(v2, v3);
    }
}

// ---------------------------------------------------------------------------
extern "C" void kernel_launch(void* const* d_in, const int* in_sizes, int n_in,
                              void* d_out, int out_size) {
    const float* x     = (const float*)d_in[0];
    const float* kv_w  = (const float*)d_in[1];
    const float* q_w   = (const float*)d_in[6];
    const float* mg_w  = (const float*)d_in[11];
    const float* fc1_w = (const float*)d_in[16];
    const float* fc2_w = (const float*)d_in[21];
    float* out = (float*)d_out;

    __half *xT, *xqT, *kv, *q, *oT, *mg, *f1;
    __half *kvw, *qw, *mgw, *fc1w, *fc2w;
    float *sc, *bi;
    cudaGetSymbolAddress((void**)&xT,   g_x16T);
    cudaGetSymbolAddress((void**)&xqT,  g_xq16T);
    cudaGetSymbolAddress((void**)&kv,   g_kv16);
    cudaGetSymbolAddress((void**)&q,    g_q16);
    cudaGetSymbolAddress((void**)&oT,   g_oT16);
    cudaGetSymbolAddress((void**)&mg,   g_mg16);
    cudaGetSymbolAddress((void**)&f1,   g_f116);
    cudaGetSymbolAddress((void**)&kvw,  g_kvw16);
    cudaGetSymbolAddress((void**)&qw,   g_qw16);
    cudaGetSymbolAddress((void**)&mgw,  g_mgw16);
    cudaGetSymbolAddress((void**)&fc1w, g_fc1w16);
    cudaGetSymbolAddress((void**)&fc2w, g_fc2w16);
    cudaGetSymbolAddress((void**)&sc,   g_sc);
    cudaGetSymbolAddress((void**)&bi,   g_bi);

    cudaFuncSetAttribute(gemm_h<false, false>, cudaFuncAttributeMaxDynamicSharedMemorySize, GH_SMEM_BYTES);
    cudaFuncSetAttribute(gemm_h<true,  false>, cudaFuncAttributeMaxDynamicSharedMemorySize, GH_SMEM_BYTES);
    cudaFuncSetAttribute(gemm_h<false, true >, cudaFuncAttributeMaxDynamicSharedMemorySize, GH_SMEM_BYTES);
    cudaFuncSetAttribute(flash_attn, cudaFuncAttributeMaxDynamicSharedMemorySize, FL_SMEM_BYTES);

    // weight conversions
    cvt16_k<<<(KVC * CIN + 255) / 256, 256>>>(kv_w, kvw, KVC * CIN);
    cvt16_k<<<(QC * CIN + 255) / 256, 256>>>(q_w, qw, QC * CIN);
    cvt16_k<<<(DOUT * MERGE + 255) / 256, 256>>>(mg_w, mgw, DOUT * MERGE);
    cvt16_k<<<(HID * DOUT + 255) / 256, 256>>>(fc1_w, fc1w, HID * DOUT);
    cvt16_k<<<(DOUT * HID + 255) / 256, 256>>>(fc2_w, fc2w, DOUT * HID);

    affine_prep<<<5, 256>>>((const float*)d_in[2], (const float*)d_in[3],
                            (const float*)d_in[4], (const float*)d_in[5],
                            sc + 0, bi + 0, KVC, 1.0f);
    affine_prep<<<1, 256>>>((const float*)d_in[7], (const float*)d_in[8],
                            (const float*)d_in[9], (const float*)d_in[10],
                            sc + 1280, bi + 1280, QC, 0.17677669529663687f);
    affine_prep<<<2, 256>>>((const float*)d_in[12], (const float*)d_in[13],
                            (const float*)d_in[14], (const float*)d_in[15],
                            sc + 1536, bi + 1536, DOUT, 1.0f);
    affine_prep<<<4, 256>>>((const float*)d_in[17], (const float*)d_in[18],
                            (const float*)d_in[19], (const float*)d_in[20],
                            sc + 2048, bi + 2048, HID, 1.0f);
    affine_prep<<<2, 256>>>((const float*)d_in[22], (const float*)d_in[23],
                            (const float*)d_in[24], (const float*)d_in[25],
                            sc + 3072, bi + 3072, DOUT, 1.0f);

    xtrans_k <<<dim3(32, 8, BATCH), dim3(32, 8)>>>(x, xT);
    xq_trans_k<<<dim3(8, 8, BATCH), dim3(32, 8)>>>(x, xqT);

    // kv = f16(BN(xT @ kv_w^T))  [b][1024][1280]
    gemm_h<false, false>
        <<<dim3(KVC / 128, NP / 128, BATCH), 256, GH_SMEM_BYTES>>>(
            xT, kvw, kv, CIN, KVC,
            (long long)NP * CIN, (long long)NP * KVC, sc + 0, bi + 0);

    // q = f16(BN(xqT @ q_w^T) * scale)  [b][256][256]
    gemm_h<false, false>
        <<<dim3(QC / 128, QP / 128, BATCH), 256, GH_SMEM_BYTES>>>(
            xqT, qw, q, CIN, QC,
            (long long)QP * CIN, (long long)QP * QC, sc + 1280, bi + 1280);

    // fused attention -> oT [b][256][1024] f16 (with gelu)
    flash_attn<<<dim3(QP / 128, BATCH * HEADS), 256, FL_SMEM_BYTES>>>(q, kv, oT);

    // mg = f16(BN(oT @ mg_w^T))  [b][256][512]
    gemm_h<false, false>
        <<<dim3(DOUT / 128, QP / 128, BATCH), 256, GH_SMEM_BYTES>>>(
            oT, mgw, mg, MERGE, DOUT,
            (long long)QP * MERGE, (long long)QP * DOUT, sc + 1536, bi + 1536);

    // f1 = f16(gelu(BN(mg @ fc1_w^T)))  [b][256][1024]
    gemm_h<true, false>
        <<<dim3(HID / 128, QP / 128, BATCH), 256, GH_SMEM_BYTES>>>(
            mg, fc1w, f1, DOUT, HID,
            (long long)QP * DOUT, (long long)QP * HID, sc + 2048, bi + 2048);

    // out = BN(f1 @ fc2_w^T)^T  f32 [b][512][256]
    gemm_h<false, true>
        <<<dim3(DOUT / 128, QP / 128, BATCH), 256, GH_SMEM_BYTES>>>(
            f1, fc2w, out, HID, QP,
            (long long)QP * HID, (long long)DOUT * QP, sc + 3072, bi + 3072);
}

// round 7
// speedup vs baseline: 6.0758x; 1.0280x over previous
#include <cuda_runtime.h>
#include <cuda_fp16.h>
#include <math.h>
#include <stdint.h>

// ---------------------------------------------------------------------------
// SubSample attention block — fp16 mma.sync (m16n8k16), position-major,
// ldmatrix fragment loads, merged prologue kernels.
// ---------------------------------------------------------------------------

constexpr int BATCH = 32, CIN = 256, NP = 1024, QP = 256;
constexpr int HEADS = 8, KD = 32, VD = 128;
constexpr int KVC = (KD + VD) * HEADS;   // 1280
constexpr int QC  = HEADS * KD;          // 256
constexpr int MERGE = HEADS * VD;        // 1024
constexpr int DOUT = 512, HID = 1024;

constexpr int HS_STAGE = 128 * 72;
constexpr int GH_SMEM_BYTES = 4 * HS_STAGE * 2;    // 73728

constexpr int FL_QS = 128 * 40;
constexpr int FL_KS = 128 * 40;
constexpr int FL_VS = 128 * 136;
constexpr int FL_SMEM_BYTES = (FL_QS + 2 * FL_KS + 2 * FL_VS) * 2;  // 100352

__device__ __align__(16) __half g_x16T [(size_t)BATCH * NP * CIN];
__device__ __align__(16) __half g_xq16T[(size_t)BATCH * QP * CIN];
__device__ __align__(16) __half g_kv16 [(size_t)BATCH * NP * KVC];
__device__ __align__(16) __half g_q16  [(size_t)BATCH * QP * QC];
__device__ __align__(16) __half g_oT16 [(size_t)BATCH * QP * MERGE];
__device__ __align__(16) __half g_mg16 [(size_t)BATCH * QP * DOUT];
__device__ __align__(16) __half g_f116 [(size_t)BATCH * QP * HID];
__device__ __align__(16) __half g_kvw16 [KVC * CIN];
__device__ __align__(16) __half g_qw16  [QC * CIN];
__device__ __align__(16) __half g_mgw16 [DOUT * MERGE];
__device__ __align__(16) __half g_fc1w16[HID * DOUT];
__device__ __align__(16) __half g_fc2w16[DOUT * HID];
__device__ float g_sc[3584];
__device__ float g_bi[3584];

__device__ __forceinline__ float gelu_exact(float x) {
    return 0.5f * x * (1.0f + erff(x * 0.70710678118654752f));
}

__device__ __forceinline__ void cpa16(void* dst, const void* src) {
    unsigned d = (unsigned)__cvta_generic_to_shared(dst);
    asm volatile("cp.async.ca.shared.global [%0], [%1], 16;\n" :: "r"(d), "l"(src));
}
__device__ __forceinline__ void cp_commit() { asm volatile("cp.async.commit_group;\n"); }
template <int W> __device__ __forceinline__ void cp_wait() {
    asm volatile("cp.async.wait_group %0;\n" :: "n"(W));
}

__device__ __forceinline__ void mma_f16(float* c, const unsigned* a, unsigned b0, unsigned b1) {
    asm volatile(
        "mma.sync.aligned.m16n8k16.row.col.f32.f16.f16.f32 "
        "{%0,%1,%2,%3}, {%4,%5,%6,%7}, {%8,%9}, {%0,%1,%2,%3};"
        : "+f"(c[0]), "+f"(c[1]), "+f"(c[2]), "+f"(c[3])
        : "r"(a[0]), "r"(a[1]), "r"(a[2]), "r"(a[3]), "r"(b0), "r"(b1));
}

__device__ __forceinline__ void ldsm4(unsigned& r0, unsigned& r1, unsigned& r2,
                                      unsigned& r3, unsigned addr) {
    asm volatile("ldmatrix.sync.aligned.m8n8.x4.shared.b16 {%0,%1,%2,%3}, [%4];"
                 : "=r"(r0), "=r"(r1), "=r"(r2), "=r"(r3) : "r"(addr));
}
__device__ __forceinline__ void ldsm_t4(unsigned& r0, unsigned& r1, unsigned& r2,
                                        unsigned& r3, unsigned addr) {
    asm volatile("ldmatrix.sync.aligned.m8n8.x4.trans.shared.b16 {%0,%1,%2,%3}, [%4];"
                 : "=r"(r0), "=r"(r1), "=r"(r2), "=r"(r3) : "r"(addr));
}

__device__ __forceinline__ unsigned packh2(float a, float b) {
    __half2 h = __floats2half2_rn(a, b);
    return *reinterpret_cast<unsigned*>(&h);
}
__device__ __forceinline__ unsigned ldu32(const __half* p) {
    return *reinterpret_cast<const unsigned*>(p);
}
__device__ __forceinline__ unsigned s2u32(const void* p) {
    unsigned a;
    asm("{ .reg .u64 tmp; cvta.to.shared.u64 tmp, %1; cvt.u32.u64 %0, tmp; }"
        : "=r"(a) : "l"(p));
    return a;
}

// ---------------------------------------------------------------------------
// merged prologue kernels
// ---------------------------------------------------------------------------
struct PrepArgs {
    const float *g[5], *b[5], *m[5], *v[5];
};
__global__ void affine_all(PrepArgs pa, float* __restrict__ sc, float* __restrict__ bi) {
    int i = blockIdx.x * 256 + threadIdx.x;
    if (i >= 3584) return;
    int seg, off;
    float mul = 1.0f;
    if (i < 1280)      { seg = 0; off = 0; }
    else if (i < 1536) { seg = 1; off = 1280; mul = 0.17677669529663687f; }
    else if (i < 2048) { seg = 2; off = 1536; }
    else if (i < 3072) { seg = 3; off = 2048; }
    else               { seg = 4; off = 3072; }
    int j = i - off;
    float s = pa.g[seg][j] * rsqrtf(pa.v[seg][j] + 1e-5f);
    sc[i] = s * mul;
    bi[i] = (pa.b[seg][j] - pa.m[seg][j] * s) * mul;
}

struct CvtArgs {
    const float* src[5];
    __half* dst[5];
    int n[5];
};
__global__ void cvt_all(CvtArgs ca) {
    int i = blockIdx.x * 256 + threadIdx.x;
#pragma unroll
    for (int s = 0; s < 5; s++) {
        if (i < ca.n[s]) { ca.dst[s][i] = __float2half_rn(ca.src[s][i]); return; }
        i -= ca.n[s];
    }
}

// x [b][256][1024] f32 -> xT [b][1024][256] f16
__global__ void xtrans_k(const float* __restrict__ x, __half* __restrict__ xT) {
    __shared__ float tile[32][33];
    int b = blockIdx.z;
    int hw0 = blockIdx.x * 32, c0 = blockIdx.y * 32;
    int tx = threadIdx.x, ty = threadIdx.y;
#pragma unroll
    for (int j = 0; j < 4; j++)
        tile[ty + 8 * j][tx] = x[((size_t)(b * CIN + c0 + ty + 8 * j) << 10) + hw0 + tx];
    __syncthreads();
#pragma unroll
    for (int j = 0; j < 4; j++)
        xT[((size_t)b * NP + hw0 + ty + 8 * j) * CIN + c0 + tx] =
            __float2half_rn(tile[tx][ty + 8 * j]);
}

__global__ void xq_trans_k(const float* __restrict__ x, __half* __restrict__ xqT) {
    __shared__ float tile[32][33];
    int b = blockIdx.z;
    int qp0 = blockIdx.x * 32, c0 = blockIdx.y * 32;
    int tx = threadIdx.x, ty = threadIdx.y;
    int qp = qp0 + tx;
    int hw = ((qp >> 4) << 6) + ((qp & 15) << 1);
#pragma unroll
    for (int j = 0; j < 4; j++)
        tile[ty + 8 * j][tx] = x[((size_t)(b * CIN + c0 + ty + 8 * j) << 10) + hw];
    __syncthreads();
#pragma unroll
    for (int j = 0; j < 4; j++)
        xqT[((size_t)b * QP + qp0 + ty + 8 * j) * CIN + c0 + tx] =
            __float2half_rn(tile[tx][ty + 8 * j]);
}

// ---------------------------------------------------------------------------
// fp16 GEMM with ldmatrix fragment loads.
// ---------------------------------------------------------------------------
template <bool GEL, bool TRANS>
__global__ __launch_bounds__(256, 2)
void gemm_h(const __half* __restrict__ A, const __half* __restrict__ B,
            void* __restrict__ Cv,
            int K, int ldc, long long sA, long long sC,
            const float* __restrict__ scale, const float* __restrict__ bias) {
    extern __shared__ __half smh[];
    __half* As = smh;
    __half* Bs = smh + 2 * HS_STAGE;

    const int t = threadIdx.x, warp = t >> 5, lane = t & 31;
    const int wm = warp & 1, wn = warp >> 1;
    const int g = lane >> 2, tq = lane & 3;
    const int bm = blockIdx.y * 128, bn = blockIdx.x * 128;

    const __half* Ab = A + (long long)blockIdx.z * sA + (long long)bm * K;
    const __half* Bb = B + (long long)bn * K;

    // ldmatrix per-thread offsets (halves)
    const int arow = ((lane >> 3) & 1) * 8 + (lane & 7);
    const int akadd = (lane >> 4) * 8;
    const int brow = (lane >> 4) * 8 + (lane & 7);
    const int bkadd = ((lane >> 3) & 1) * 8;
    const unsigned as_u32 = s2u32(As);
    const unsigned bs_u32 = s2u32(Bs);

    auto ldtile = [&](int s, int k0) {
#pragma unroll
        for (int j = 0; j < 4; j++) {
            int idx = j * 256 + t;
            int r = idx >> 3, c = idx & 7;
            cpa16(As + s * HS_STAGE + r * 72 + c * 8, Ab + (long long)r * K + k0 + c * 8);
            cpa16(Bs + s * HS_STAGE + r * 72 + c * 8, Bb + (long long)r * K + k0 + c * 8);
        }
    };

    float acc[4][4][4];
#pragma unroll
    for (int i = 0; i < 4; i++)
#pragma unroll
        for (int j = 0; j < 4; j++)
#pragma unroll
            for (int r = 0; r < 4; r++) acc[i][j][r] = 0.0f;

    const int niter = K >> 6;
    ldtile(0, 0);
    cp_commit();

    for (int it = 0; it < niter; it++) {
        const int s = it & 1;
        if (it + 1 < niter) ldtile(s ^ 1, (it + 1) << 6);
        cp_commit();
        cp_wait<1>();
        __syncthreads();

        const unsigned as0 = as_u32 + (unsigned)(s * HS_STAGE * 2);
        const unsigned bs0 = bs_u32 + (unsigned)(s * HS_STAGE * 2);
#pragma unroll
        for (int kb = 0; kb < 4; kb++) {
            const int ko = kb * 16;
            unsigned a[4][4];
#pragma unroll
            for (int mi = 0; mi < 4; mi++)
                ldsm4(a[mi][0], a[mi][1], a[mi][2], a[mi][3],
                      as0 + 2u * (unsigned)((wm * 64 + mi * 16 + arow) * 72 + ko + akadd));
            unsigned b[4][2];
#pragma unroll
            for (int nip = 0; nip < 2; nip++)
                ldsm4(b[2 * nip][0], b[2 * nip][1], b[2 * nip + 1][0], b[2 * nip + 1][1],
                      bs0 + 2u * (unsigned)((wn * 32 + nip * 16 + brow) * 72 + ko + bkadd));
#pragma unroll
            for (int mi = 0; mi < 4; mi++)
#pragma unroll
                for (int ni = 0; ni < 4; ni++)
                    mma_f16(acc[mi][ni], a[mi], b[ni][0], b[ni][1]);
        }
        __syncthreads();
    }

    if (!TRANS) {
        __half* Cb = reinterpret_cast<__half*>(Cv) + (long long)blockIdx.z * sC;
#pragma unroll
        for (int mi = 0; mi < 4; mi++) {
            int r0 = bm + wm * 64 + mi * 16 + g;
            int r1 = r0 + 8;
#pragma unroll
            for (int ni = 0; ni < 4; ni++) {
                int col = bn + wn * 32 + ni * 8 + 2 * tq;
                float s0 = scale[col], b0s = bias[col];
                float s1 = scale[col + 1], b1s = bias[col + 1];
                float v0 = fmaf(acc[mi][ni][0], s0, b0s);
                float v1 = fmaf(acc[mi][ni][1], s1, b1s);
                float v2 = fmaf(acc[mi][ni][2], s0, b0s);
                float v3 = fmaf(acc[mi][ni][3], s1, b1s);
                if (GEL) {
                    v0 = gelu_exact(v0); v1 = gelu_exact(v1);
                    v2 = gelu_exact(v2); v3 = gelu_exact(v3);
                }
                *reinterpret_cast<unsigned*>(Cb + (long long)r0 * ldc + col) = packh2(v0, v1);
                *reinterpret_cast<unsigned*>(Cb + (long long)r1 * ldc + col) = packh2(v2, v3);
            }
        }
    } else {
        float* Cs = reinterpret_cast<float*>(smh);   // [128][133]
        __syncthreads();
#pragma unroll
        for (int mi = 0; mi < 4; mi++) {
            int r0 = wm * 64 + mi * 16 + g;
            int r1 = r0 + 8;
#pragma unroll
            for (int ni = 0; ni < 4; ni++) {
                int col = wn * 32 + ni * 8 + 2 * tq;
                int cg = bn + col;
                float s0 = scale[cg], b0s = bias[cg];
                float s1 = scale[cg + 1], b1s = bias[cg + 1];
                Cs[r0 * 133 + col]     = fmaf(acc[mi][ni][0], s0, b0s);
                Cs[r0 * 133 + col + 1] = fmaf(acc[mi][ni][1], s1, b1s);
                Cs[r1 * 133 + col]     = fmaf(acc[mi][ni][2], s0, b0s);
                Cs[r1 * 133 + col + 1] = fmaf(acc[mi][ni][3], s1, b1s);
            }
        }
        __syncthreads();
        float* Cb = reinterpret_cast<float*>(Cv) + (long long)blockIdx.z * sC;
        int n = t >> 1;
        int m0 = (t & 1) * 64;
        float* orow = Cb + (long long)(bn + n) * ldc + bm + m0;
#pragma unroll
        for (int i = 0; i < 16; i++) {
            float4 v;
            v.x = Cs[(m0 + i * 4 + 0) * 133 + n];
            v.y = Cs[(m0 + i * 4 + 1) * 133 + n];
            v.z = Cs[(m0 + i * 4 + 2) * 133 + n];
            v.w = Cs[(m0 + i * 4 + 3) * 133 + n];
            *reinterpret_cast<float4*>(orow + i * 4) = v;
        }
    }
}

// ---------------------------------------------------------------------------
// Flash attention fp16 with ldmatrix K-fragments.
// ---------------------------------------------------------------------------
__global__ __launch_bounds__(256, 1)
void flash_attn(const __half* __restrict__ q, const __half* __restrict__ kv,
                __half* __restrict__ oT) {
    const int t    = threadIdx.x;
    const int warp = t >> 5, lane = t & 31;
    const int g    = lane >> 2, tq = lane & 3;
    const int bh   = blockIdx.y;
    const int b    = bh >> 3, h = bh & 7;
    const int q0   = blockIdx.x * 128;

    extern __shared__ __half smh[];
    __half* Qs = smh;               // [128 qp][40]
    __half* Ks = Qs + FL_QS;        // [2][128 n][40]
    __half* Vs = Ks + 2 * FL_KS;    // [2][128 n][136]

    const __half* kvb = kv + (size_t)b * NP * KVC + h * (KD + VD);

    auto loadKV = [&](int s, int n0) {
        __half* ks = Ks + s * FL_KS;
#pragma unroll
        for (int j = 0; j < 2; j++) {
            int idx = j * 256 + t;
            int n = idx >> 2, c = idx & 3;
            cpa16(ks + n * 40 + c * 8, kvb + (size_t)(n0 + n) * KVC + c * 8);
        }
        __half* vs = Vs + s * FL_VS;
#pragma unroll
        for (int j = 0; j < 8; j++) {
            int idx = j * 256 + t;
            int n = idx >> 4, c = idx & 15;
            cpa16(vs + n * 136 + c * 8, kvb + (size_t)(n0 + n) * KVC + KD + c * 8);
        }
    };

#pragma unroll
    for (int j = 0; j < 2; j++) {
        int idx = j * 256 + t;
        int r = idx >> 2, c = idx & 3;
        cpa16(Qs + r * 40 + c * 8, q + ((size_t)b * QP + q0 + r) * QC + h * KD + c * 8);
    }
    loadKV(0, 0);
    cp_commit();

    unsigned aq[2][4];
    float m0 = -1e30f, m1 = -1e30f, l0 = 0.0f, l1 = 0.0f;
    float o[16][4];
#pragma unroll
    for (int j = 0; j < 16; j++)
#pragma unroll
        for (int r = 0; r < 4; r++) o[j][r] = 0.0f;

    // ldmatrix per-thread offsets
    const int brow = (lane >> 4) * 8 + (lane & 7);         // S-loop K frags
    const int bkadd = ((lane >> 3) & 1) * 8;
    const int lmi = lane >> 3, lrow = lane & 7;            // PV trans frags
    const int ldrow = ((lmi & 1) * 8 + lrow) * 136 + (lmi >> 1) * 8;

    for (int blk = 0; blk < 8; blk++) {
        const int s = blk & 1;
        if (blk + 1 < 8) loadKV(s ^ 1, (blk + 1) * 128);
        cp_commit();
        cp_wait<1>();
        __syncthreads();

        if (blk == 0) {
#pragma unroll
            for (int kb = 0; kb < 2; kb++) {
                int r = warp * 16 + g;
                aq[kb][0] = ldu32(Qs + r * 40 + kb * 16 + 2 * tq);
                aq[kb][1] = ldu32(Qs + (r + 8) * 40 + kb * 16 + 2 * tq);
                aq[kb][2] = ldu32(Qs + r * 40 + kb * 16 + 2 * tq + 8);
                aq[kb][3] = ldu32(Qs + (r + 8) * 40 + kb * 16 + 2 * tq + 8);
            }
        }

        const unsigned ks_u32 = s2u32(Ks + s * FL_KS);
        const unsigned vs_u32 = s2u32(Vs + s * FL_VS);

        // S = Q @ K^T  (ldmatrix x4 per ni-pair per kb)
        float p[16][4];
#pragma unroll
        for (int ni = 0; ni < 16; ni++)
            p[ni][0] = p[ni][1] = p[ni][2] = p[ni][3] = 0.0f;
#pragma unroll
        for (int kb = 0; kb < 2; kb++) {
#pragma unroll
            for (int nip = 0; nip < 8; nip++) {
                unsigned b00, b01, b10, b11;
                ldsm4(b00, b01, b10, b11,
                      ks_u32 + 2u * (unsigned)((nip * 16 + brow) * 40 + kb * 16 + bkadd));
                mma_f16(p[2 * nip],     aq[kb], b00, b01);
                mma_f16(p[2 * nip + 1], aq[kb], b10, b11);
            }
        }

        // online softmax
        float bm0 = -1e30f, bm1 = -1e30f;
#pragma unroll
        for (int ni = 0; ni < 16; ni++) {
            bm0 = fmaxf(bm0, fmaxf(p[ni][0], p[ni][1]));
            bm1 = fmaxf(bm1, fmaxf(p[ni][2], p[ni][3]));
        }
        bm0 = fmaxf(bm0, __shfl_xor_sync(0xffffffffu, bm0, 1));
        bm0 = fmaxf(bm0, __shfl_xor_sync(0xffffffffu, bm0, 2));
        bm1 = fmaxf(bm1, __shfl_xor_sync(0xffffffffu, bm1, 1));
        bm1 = fmaxf(bm1, __shfl_xor_sync(0xffffffffu, bm1, 2));
        float mn0 = fmaxf(m0, bm0), mn1 = fmaxf(m1, bm1);
        float al0 = __expf(m0 - mn0), al1 = __expf(m1 - mn1);
        float rs0 = 0.0f, rs1 = 0.0f;
#pragma unroll
        for (int ni = 0; ni < 16; ni++) {
            p[ni][0] = __expf(p[ni][0] - mn0);
            p[ni][1] = __expf(p[ni][1] - mn0);
            p[ni][2] = __expf(p[ni][2] - mn1);
            p[ni][3] = __expf(p[ni][3] - mn1);
            rs0 += p[ni][0] + p[ni][1];
            rs1 += p[ni][2] + p[ni][3];
        }
        rs0 += __shfl_xor_sync(0xffffffffu, rs0, 1);
        rs0 += __shfl_xor_sync(0xffffffffu, rs0, 2);
        rs1 += __shfl_xor_sync(0xffffffffu, rs1, 1);
        rs1 += __shfl_xor_sync(0xffffffffu, rs1, 2);
        l0 = l0 * al0 + rs0;
        l1 = l1 * al1 + rs1;
        m0 = mn0; m1 = mn1;
#pragma unroll
        for (int j = 0; j < 16; j++) {
            o[j][0] *= al0; o[j][1] *= al0;
            o[j][2] *= al1; o[j][3] *= al1;
        }

        // P @ V
#pragma unroll
        for (int ki = 0; ki < 8; ki++) {
            unsigned ap[4];
            ap[0] = packh2(p[2 * ki][0],     p[2 * ki][1]);
            ap[1] = packh2(p[2 * ki][2],     p[2 * ki][3]);
            ap[2] = packh2(p[2 * ki + 1][0], p[2 * ki + 1][1]);
            ap[3] = packh2(p[2 * ki + 1][2], p[2 * ki + 1][3]);
#pragma unroll
            for (int jj = 0; jj < 8; jj++) {
                unsigned r0, r1, r2, r3;
                ldsm_t4(r0, r1, r2, r3,
                        vs_u32 + 2u * (unsigned)(ki * 16 * 136 + jj * 16 + ldrow));
                mma_f16(o[2 * jj],     ap, r0, r1);
                mma_f16(o[2 * jj + 1], ap, r2, r3);
            }
        }
        __syncthreads();
    }

    float inv0 = 1.0f / l0, inv1 = 1.0f / l1;
    int r0 = q0 + warp * 16 + g;
    int r1 = r0 + 8;
    __half* orow0 = oT + ((size_t)b * QP + r0) * MERGE + h * VD;
    __half* orow1 = oT + ((size_t)b * QP + r1) * MERGE + h * VD;
#pragma unroll
    for (int j = 0; j < 16; j++) {
        int col = j * 8 + 2 * tq;
        float v0 = gelu_exact(o[j][0] * inv0);
        float v1 = gelu_exact(o[j][1] * inv0);
        float v2 = gelu_exact(o[j][2] * inv1);
        float v3 = gelu_exact(o[j][3] * inv1);
        *reinterpret_cast<unsigned*>(orow0 + col) = packh2(v0, v1);
        *reinterpret_cast<unsigned*>(orow1 + col) = packh2(v2, v3);
    }
}

// ---------------------------------------------------------------------------
extern "C" void kernel_launch(void* const* d_in, const int* in_sizes, int n_in,
                              void* d_out, int out_size) {
    const float* x     = (const float*)d_in[0];
    const float* kv_w  = (const float*)d_in[1];
    const float* q_w   = (const float*)d_in[6];
    const float* mg_w  = (const float*)d_in[11];
    const float* fc1_w = (const float*)d_in[16];
    const float* fc2_w = (const float*)d_in[21];
    float* out = (float*)d_out;

    __half *xT, *xqT, *kv, *q, *oT, *mg, *f1;
    __half *kvw, *qw, *mgw, *fc1w, *fc2w;
    float *sc, *bi;
    cudaGetSymbolAddress((void**)&xT,   g_x16T);
    cudaGetSymbolAddress((void**)&xqT,  g_xq16T);
    cudaGetSymbolAddress((void**)&kv,   g_kv16);
    cudaGetSymbolAddress((void**)&q,    g_q16);
    cudaGetSymbolAddress((void**)&oT,   g_oT16);
    cudaGetSymbolAddress((void**)&mg,   g_mg16);
    cudaGetSymbolAddress((void**)&f1,   g_f116);
    cudaGetSymbolAddress((void**)&kvw,  g_kvw16);
    cudaGetSymbolAddress((void**)&qw,   g_qw16);
    cudaGetSymbolAddress((void**)&mgw,  g_mgw16);
    cudaGetSymbolAddress((void**)&fc1w, g_fc1w16);
    cudaGetSymbolAddress((void**)&fc2w, g_fc2w16);
    cudaGetSymbolAddress((void**)&sc,   g_sc);
    cudaGetSymbolAddress((void**)&bi,   g_bi);

    cudaFuncSetAttribute(gemm_h<false, false>, cudaFuncAttributeMaxDynamicSharedMemorySize, GH_SMEM_BYTES);
    cudaFuncSetAttribute(gemm_h<true,  false>, cudaFuncAttributeMaxDynamicSharedMemorySize, GH_SMEM_BYTES);
    cudaFuncSetAttribute(gemm_h<false, true >, cudaFuncAttributeMaxDynamicSharedMemorySize, GH_SMEM_BYTES);
    cudaFuncSetAttribute(flash_attn, cudaFuncAttributeMaxDynamicSharedMemorySize, FL_SMEM_BYTES);

    // merged weight conversion (1 launch)
    {
        CvtArgs ca;
        ca.src[0] = kv_w;  ca.dst[0] = kvw;  ca.n[0] = KVC * CIN;
        ca.src[1] = q_w;   ca.dst[1] = qw;   ca.n[1] = QC * CIN;
        ca.src[2] = mg_w;  ca.dst[2] = mgw;  ca.n[2] = DOUT * MERGE;
        ca.src[3] = fc1_w; ca.dst[3] = fc1w; ca.n[3] = HID * DOUT;
        ca.src[4] = fc2_w; ca.dst[4] = fc2w; ca.n[4] = DOUT * HID;
        int total = ca.n[0] + ca.n[1] + ca.n[2] + ca.n[3] + ca.n[4];
        cvt_all<<<(total + 255) / 256, 256>>>(ca);
    }
    // merged BN fold (1 launch)
    {
        PrepArgs pa;
        const int base[5] = {2, 7, 12, 17, 22};
#pragma unroll
        for (int s = 0; s < 5; s++) {
            pa.g[s] = (const float*)d_in[base[s] + 0];
            pa.b[s] = (const float*)d_in[base[s] + 1];
            pa.m[s] = (const float*)d_in[base[s] + 2];
            pa.v[s] = (const float*)d_in[base[s] + 3];
        }
        affine_all<<<14, 256>>>(pa, sc, bi);
    }

    xtrans_k <<<dim3(32, 8, BATCH), dim3(32, 8)>>>(x, xT);
    xq_trans_k<<<dim3(8, 8, BATCH), dim3(32, 8)>>>(x, xqT);

    // kv = f16(BN(xT @ kv_w^T))
    gemm_h<false, false>
        <<<dim3(KVC / 128, NP / 128, BATCH), 256, GH_SMEM_BYTES>>>(
            xT, kvw, kv, CIN, KVC,
            (long long)NP * CIN, (long long)NP * KVC, sc + 0, bi + 0);

    // q = f16(BN(xqT @ q_w^T) * scale)
    gemm_h<false, false>
        <<<dim3(QC / 128, QP / 128, BATCH), 256, GH_SMEM_BYTES>>>(
            xqT, qw, q, CIN, QC,
            (long long)QP * CIN, (long long)QP * QC, sc + 1280, bi + 1280);

    // fused attention -> oT
    flash_attn<<<dim3(QP / 128, BATCH * HEADS), 256, FL_SMEM_BYTES>>>(q, kv, oT);

    // mg = f16(BN(oT @ mg_w^T))
    gemm_h<false, false>
        <<<dim3(DOUT / 128, QP / 128, BATCH), 256, GH_SMEM_BYTES>>>(
            oT, mgw, mg, MERGE, DOUT,
            (long long)QP * MERGE, (long long)QP * DOUT, sc + 1536, bi + 1536);

    // f1 = f16(gelu(BN(mg @ fc1_w^T)))
    gemm_h<true, false>
        <<<dim3(HID / 128, QP / 128, BATCH), 256, GH_SMEM_BYTES>>>(
            mg, fc1w, f1, DOUT, HID,
            (long long)QP * DOUT, (long long)QP * HID, sc + 2048, bi + 2048);

    // out = BN(f1 @ fc2_w^T)^T  f32
    gemm_h<false, true>
        <<<dim3(DOUT / 128, QP / 128, BATCH), 256, GH_SMEM_BYTES>>>(
            f1, fc2w, out, HID, QP,
            (long long)QP * HID, (long long)DOUT * QP, sc + 3072, bi + 3072);
}